// round 1
// baseline (speedup 1.0000x reference)
#include <cuda_runtime.h>
#include <math.h>

#define Bv 8
#define Cv 256
#define NW 1024      // 32*32 super tokens
#define GW 32
#define NHEADS 8
#define HD 32

// ---------------- scratch (static device memory; no allocs) ----------------
__device__ float g_wf[Bv * NW * Cv];           // (b, t, c)          8 MB
__device__ float g_aff[Bv * NW * 16 * 9];      // (b, t, p, i)       4.5 MB
__device__ float g_wf2raw[(size_t)Bv * NW * 9 * Cv]; // (b, t, i, c) 75.5 MB
__device__ float g_affsumraw[Bv * NW * 9];     // (b, t, i)
__device__ float g_wf2[Bv * NW * Cv];          // (b, t, c)          8 MB
__device__ float g_qkv[(size_t)Bv * 768 * NW]; // (b, o, n)          25 MB
__device__ float g_attn_out[(size_t)Bv * Cv * NW]; // (b, c, n)      8 MB
__device__ float g_proj[(size_t)Bv * NW * Cv]; // (b, n, o)          8 MB

// ---------------- kernel 1: 4x4 average pool -> wf ----------------
__global__ void pool_kernel(const float* __restrict__ x) {
    int b = blockIdx.y, t = blockIdx.x, c = threadIdx.x;
    int Y = t >> 5, X = t & 31;
    const float* xb = x + (size_t)b * 16384 * 256;
    float s = 0.f;
#pragma unroll
    for (int py = 0; py < 4; py++)
#pragma unroll
        for (int px = 0; px < 4; px++) {
            int n = (Y * 4 + py) * 128 + X * 4 + px;
            s += xb[(size_t)n * 256 + c];
        }
    g_wf[((size_t)b * NW + t) * Cv + c] = s * (1.f / 16.f);
}

// ---------------- kernel 2: affinity softmax + wf2 window partials ----------
__global__ void aff_kernel(const float* __restrict__ x) {
    __shared__ float pix[16][256];
    __shared__ float wfu[9][256];
    __shared__ float lg[16][9];
    __shared__ float affs[16][9];
    int b = blockIdx.y, t = blockIdx.x, tid = threadIdx.x;
    int Y = t >> 5, X = t & 31;
    const float* xb = x + (size_t)b * 16384 * 256;
#pragma unroll
    for (int p = 0; p < 16; p++) {
        int n = (Y * 4 + (p >> 2)) * 128 + X * 4 + (p & 3);
        pix[p][tid] = xb[(size_t)n * 256 + tid];
    }
#pragma unroll
    for (int i = 0; i < 9; i++) {
        int ny = Y + (i / 3) - 1, nx = X + (i % 3) - 1;
        float v = 0.f;
        if ((unsigned)ny < 32u && (unsigned)nx < 32u)
            v = g_wf[((size_t)b * NW + ny * 32 + nx) * Cv + tid];
        wfu[i][tid] = v;
    }
    __syncthreads();
    int warp = tid >> 5, lane = tid & 31;
    for (int pair = warp; pair < 144; pair += 8) {
        int p = pair / 9, i = pair % 9;
        float s = 0.f;
#pragma unroll
        for (int k = 0; k < 8; k++) s += pix[p][lane + 32 * k] * wfu[i][lane + 32 * k];
#pragma unroll
        for (int off = 16; off; off >>= 1) s += __shfl_down_sync(0xffffffffu, s, off);
        if (lane == 0) lg[p][i] = s * 0.0625f;   // scale = C^{-1/2} = 1/16
    }
    __syncthreads();
    if (tid < 16) {
        float m = -1e30f;
#pragma unroll
        for (int i = 0; i < 9; i++) m = fmaxf(m, lg[tid][i]);
        float e[9], sum = 0.f;
#pragma unroll
        for (int i = 0; i < 9; i++) { e[i] = __expf(lg[tid][i] - m); sum += e[i]; }
        float inv = 1.f / sum;
#pragma unroll
        for (int i = 0; i < 9; i++) affs[tid][i] = e[i] * inv;
    }
    __syncthreads();
    if (tid < 144)
        g_aff[((size_t)b * NW + t) * 144 + tid] = affs[tid / 9][tid % 9];
    if (tid >= 160 && tid < 169) {
        int i = tid - 160;
        float s = 0.f;
#pragma unroll
        for (int p = 0; p < 16; p++) s += affs[p][i];
        g_affsumraw[((size_t)b * NW + t) * 9 + i] = s;
    }
    // wf2 window partials: thread = channel
    float acc[9];
#pragma unroll
    for (int i = 0; i < 9; i++) acc[i] = 0.f;
#pragma unroll
    for (int p = 0; p < 16; p++) {
        float v = pix[p][tid];
#pragma unroll
        for (int i = 0; i < 9; i++) acc[i] = fmaf(v, affs[p][i], acc[i]);
    }
    size_t base = ((size_t)b * NW + t) * 9 * Cv;
#pragma unroll
    for (int i = 0; i < 9; i++) g_wf2raw[base + (size_t)i * Cv + tid] = acc[i];
}

// ---------------- kernel 3: fold-gather + normalize ----------------
__global__ void fold_kernel() {
    int b = blockIdx.y, t = blockIdx.x, c = threadIdx.x;
    int Y = t >> 5, X = t & 31;
    float acc = 0.f, asum = 0.f;
#pragma unroll
    for (int i = 0; i < 9; i++) {
        int ny = Y - ((i / 3) - 1), nx = X - ((i % 3) - 1);
        if ((unsigned)ny < 32u && (unsigned)nx < 32u) {
            size_t nb = (size_t)b * NW + ny * 32 + nx;
            acc += g_wf2raw[(nb * 9 + i) * Cv + c];
            asum += g_affsumraw[nb * 9 + i];
        }
    }
    g_wf2[((size_t)b * NW + t) * Cv + c] = acc / (asum + 1e-12f);
}

// ---------------- kernel 4: qkv GEMM (768x1024x256 per batch, NT) -----------
__global__ void gemm_qkv(const float* __restrict__ W) {
    __shared__ float As[64][65];
    __shared__ float Bs[64][65];
    int b = blockIdx.z;
    int o0 = blockIdx.y * 64, n0 = blockIdx.x * 64;
    int tid = threadIdx.x, tx = tid & 15, ty = tid >> 4;
    float c[4][4] = {};
    const float* Bp = g_wf2 + (size_t)b * NW * Cv;
    for (int k0 = 0; k0 < 256; k0 += 64) {
        __syncthreads();
#pragma unroll
        for (int l = 0; l < 4; l++) {
            int e = tid + l * 256;
            int row = e >> 4, kq = e & 15;
            float4 a4 = *(const float4*)&W[(size_t)(o0 + row) * 256 + k0 + kq * 4];
            As[kq * 4 + 0][row] = a4.x; As[kq * 4 + 1][row] = a4.y;
            As[kq * 4 + 2][row] = a4.z; As[kq * 4 + 3][row] = a4.w;
            float4 b4 = *(const float4*)&Bp[(size_t)(n0 + row) * 256 + k0 + kq * 4];
            Bs[kq * 4 + 0][row] = b4.x; Bs[kq * 4 + 1][row] = b4.y;
            Bs[kq * 4 + 2][row] = b4.z; Bs[kq * 4 + 3][row] = b4.w;
        }
        __syncthreads();
#pragma unroll 8
        for (int k = 0; k < 64; k++) {
            float a0 = As[k][ty * 4 + 0], a1 = As[k][ty * 4 + 1];
            float a2 = As[k][ty * 4 + 2], a3 = As[k][ty * 4 + 3];
            float b0 = Bs[k][tx * 4 + 0], b1 = Bs[k][tx * 4 + 1];
            float b2 = Bs[k][tx * 4 + 2], b3 = Bs[k][tx * 4 + 3];
            c[0][0] = fmaf(a0, b0, c[0][0]); c[0][1] = fmaf(a0, b1, c[0][1]);
            c[0][2] = fmaf(a0, b2, c[0][2]); c[0][3] = fmaf(a0, b3, c[0][3]);
            c[1][0] = fmaf(a1, b0, c[1][0]); c[1][1] = fmaf(a1, b1, c[1][1]);
            c[1][2] = fmaf(a1, b2, c[1][2]); c[1][3] = fmaf(a1, b3, c[1][3]);
            c[2][0] = fmaf(a2, b0, c[2][0]); c[2][1] = fmaf(a2, b1, c[2][1]);
            c[2][2] = fmaf(a2, b2, c[2][2]); c[2][3] = fmaf(a2, b3, c[2][3]);
            c[3][0] = fmaf(a3, b0, c[3][0]); c[3][1] = fmaf(a3, b1, c[3][1]);
            c[3][2] = fmaf(a3, b2, c[3][2]); c[3][3] = fmaf(a3, b3, c[3][3]);
        }
    }
#pragma unroll
    for (int mm = 0; mm < 4; mm++) {
        float4 v = make_float4(c[mm][0], c[mm][1], c[mm][2], c[mm][3]);
        *(float4*)&g_qkv[((size_t)b * 768 + o0 + ty * 4 + mm) * NW + n0 + tx * 4] = v;
    }
}

// ---------------- kernel 5: attention (softmax over keys), flash-style ------
__global__ void __launch_bounds__(256) attn_kernel() {
    __shared__ float ks[128][36];
    __shared__ float vs[128][36];
    int b = blockIdx.z, h = blockIdx.y, chunk = blockIdx.x;
    int tid = threadIdx.x;
    int m = chunk * 256 + tid;
    const float* qp = g_qkv + ((size_t)b * 768 + h * 96) * NW;
    const float* kp = qp + (size_t)32 * NW;
    const float* vp = qp + (size_t)64 * NW;
    float q[32];
#pragma unroll
    for (int d = 0; d < 32; d++) q[d] = qp[(size_t)d * NW + m] * 0.17677669529663687f;
    float mmax = -INFINITY, l = 0.f, acc[32];
#pragma unroll
    for (int d = 0; d < 32; d++) acc[d] = 0.f;
    for (int n0 = 0; n0 < 1024; n0 += 128) {
        __syncthreads();
        for (int e = tid; e < 32 * 128; e += 256) {
            int d = e >> 7, n = e & 127;
            ks[n][d] = kp[(size_t)d * NW + n0 + n];
            vs[n][d] = vp[(size_t)d * NW + n0 + n];
        }
        __syncthreads();
#pragma unroll 2
        for (int n = 0; n < 128; n++) {
            float s = 0.f;
#pragma unroll
            for (int d4 = 0; d4 < 8; d4++) {
                float4 kk = *(const float4*)&ks[n][d4 * 4];
                s = fmaf(q[d4 * 4 + 0], kk.x, s);
                s = fmaf(q[d4 * 4 + 1], kk.y, s);
                s = fmaf(q[d4 * 4 + 2], kk.z, s);
                s = fmaf(q[d4 * 4 + 3], kk.w, s);
            }
            float p;
            if (s > mmax) {
                float corr = __expf(mmax - s);
                mmax = s;
                l *= corr;
#pragma unroll
                for (int d = 0; d < 32; d++) acc[d] *= corr;
                p = 1.f;
            } else {
                p = __expf(s - mmax);
            }
            l += p;
#pragma unroll
            for (int d4 = 0; d4 < 8; d4++) {
                float4 vv = *(const float4*)&vs[n][d4 * 4];
                acc[d4 * 4 + 0] = fmaf(p, vv.x, acc[d4 * 4 + 0]);
                acc[d4 * 4 + 1] = fmaf(p, vv.y, acc[d4 * 4 + 1]);
                acc[d4 * 4 + 2] = fmaf(p, vv.z, acc[d4 * 4 + 2]);
                acc[d4 * 4 + 3] = fmaf(p, vv.w, acc[d4 * 4 + 3]);
            }
        }
    }
    float inv = 1.f / l;
    float* op = g_attn_out + ((size_t)b * Cv + h * 32) * NW + m;
#pragma unroll
    for (int d = 0; d < 32; d++) op[(size_t)d * NW] = acc[d] * inv;
}

// ---------------- kernel 6: proj GEMM (+bias), output token-major -----------
__global__ void gemm_proj(const float* __restrict__ Wp, const float* __restrict__ bias) {
    __shared__ float sm[2 * 64 * 65];
    float (*As)[65] = (float(*)[65])sm;
    float (*Bs)[65] = (float(*)[65])(sm + 64 * 65);
    int b = blockIdx.z, o0 = blockIdx.y * 64, n0 = blockIdx.x * 64;
    int tid = threadIdx.x, tx = tid & 15, ty = tid >> 4;
    float c[4][4] = {};
    const float* Bg = g_attn_out + (size_t)b * Cv * NW;
    for (int k0 = 0; k0 < 256; k0 += 64) {
        __syncthreads();
#pragma unroll
        for (int l = 0; l < 4; l++) {
            int e = tid + l * 256;
            int row = e >> 4, q4 = e & 15;
            float4 a4 = *(const float4*)&Wp[(size_t)(o0 + row) * 256 + k0 + q4 * 4];
            As[q4 * 4 + 0][row] = a4.x; As[q4 * 4 + 1][row] = a4.y;
            As[q4 * 4 + 2][row] = a4.z; As[q4 * 4 + 3][row] = a4.w;
            float4 b4 = *(const float4*)&Bg[(size_t)(k0 + row) * NW + n0 + q4 * 4];
            Bs[row][q4 * 4 + 0] = b4.x; Bs[row][q4 * 4 + 1] = b4.y;
            Bs[row][q4 * 4 + 2] = b4.z; Bs[row][q4 * 4 + 3] = b4.w;
        }
        __syncthreads();
#pragma unroll 8
        for (int k = 0; k < 64; k++) {
            float a0 = As[k][ty * 4 + 0], a1 = As[k][ty * 4 + 1];
            float a2 = As[k][ty * 4 + 2], a3 = As[k][ty * 4 + 3];
            float b0 = Bs[k][tx * 4 + 0], b1 = Bs[k][tx * 4 + 1];
            float b2 = Bs[k][tx * 4 + 2], b3 = Bs[k][tx * 4 + 3];
            c[0][0] = fmaf(a0, b0, c[0][0]); c[0][1] = fmaf(a0, b1, c[0][1]);
            c[0][2] = fmaf(a0, b2, c[0][2]); c[0][3] = fmaf(a0, b3, c[0][3]);
            c[1][0] = fmaf(a1, b0, c[1][0]); c[1][1] = fmaf(a1, b1, c[1][1]);
            c[1][2] = fmaf(a1, b2, c[1][2]); c[1][3] = fmaf(a1, b3, c[1][3]);
            c[2][0] = fmaf(a2, b0, c[2][0]); c[2][1] = fmaf(a2, b1, c[2][1]);
            c[2][2] = fmaf(a2, b2, c[2][2]); c[2][3] = fmaf(a2, b3, c[2][3]);
            c[3][0] = fmaf(a3, b0, c[3][0]); c[3][1] = fmaf(a3, b1, c[3][1]);
            c[3][2] = fmaf(a3, b2, c[3][2]); c[3][3] = fmaf(a3, b3, c[3][3]);
        }
    }
    __syncthreads();
    float* Cs = sm;   // reuse as [n][o] with stride 65
#pragma unroll
    for (int mm = 0; mm < 4; mm++)
#pragma unroll
        for (int nn = 0; nn < 4; nn++)
            Cs[(tx * 4 + nn) * 65 + ty * 4 + mm] = c[mm][nn];
    __syncthreads();
#pragma unroll
    for (int l = 0; l < 16; l++) {
        int e = tid + l * 256;
        int nl = e >> 6, ol = e & 63;
        g_proj[((size_t)b * NW + n0 + nl) * Cv + o0 + ol] = Cs[nl * 65 + ol] + bias[o0 + ol];
    }
}

// ---------------- kernel 7: scatter back to pixels, planar output -----------
__global__ void scatter_kernel(float* __restrict__ out) {
    __shared__ float aff_s[32 * 144];         // row of 32 windows
    __shared__ float r_s[3 * 34 * 33];        // [dy][X+1 (0..33)][c-chunk(32)+pad]
    int Y = blockIdx.x, b = blockIdx.y;
    int tid = threadIdx.x;               // 128 threads = w in [0,128)
    int X = tid >> 2, px = tid & 3;
    // load affinity row (contiguous)
    const float* ab = g_aff + ((size_t)b * NW + Y * 32) * 144;
    for (int idx = tid; idx < 4608; idx += 128) aff_s[idx] = ab[idx];
    // zero full r_s once (borders + invalid rows stay zero)
    for (int idx = tid; idx < 3 * 34 * 33; idx += 128) r_s[idx] = 0.f;
    __syncthreads();
    float a[4][9];
#pragma unroll
    for (int py = 0; py < 4; py++)
#pragma unroll
        for (int i = 0; i < 9; i++)
            a[py][i] = aff_s[X * 144 + (py * 4 + px) * 9 + i];

    for (int c0 = 0; c0 < 256; c0 += 32) {
        __syncthreads();
        for (int idx = tid; idx < 3 * 32 * 32; idx += 128) {
            int dy = idx >> 10;
            int rem = idx & 1023;
            int Xl = rem >> 5, cc = rem & 31;
            int ny = Y + dy - 1;
            if ((unsigned)ny < 32u)
                r_s[((dy * 34) + Xl + 1) * 33 + cc] =
                    g_proj[((size_t)b * NW + ny * 32 + Xl) * Cv + c0 + cc];
        }
        __syncthreads();
#pragma unroll
        for (int py = 0; py < 4; py++) {
            size_t obase = ((size_t)b * 256 + c0) * 16384 +
                           (size_t)(Y * 4 + py) * 128 + tid;
#pragma unroll 4
            for (int c = 0; c < 32; c++) {
                float v = 0.f;
#pragma unroll
                for (int i = 0; i < 9; i++) {
                    int dy = i / 3, dx = i % 3;
                    v = fmaf(r_s[((dy * 34) + X + dx) * 33 + c], a[py][i], v);
                }
                out[obase + (size_t)c * 16384] = v;
            }
        }
    }
}

// ---------------- launch ----------------
extern "C" void kernel_launch(void* const* d_in, const int* in_sizes, int n_in,
                              void* d_out, int out_size) {
    // defensive input selection by element count
    const float* x = nullptr; const float* qkv_w = nullptr;
    const float* proj_w = nullptr; const float* proj_b = nullptr;
    for (int i = 0; i < n_in; i++) {
        int s = in_sizes[i];
        if (s == 8 * 16384 * 256) x = (const float*)d_in[i];
        else if (s == 768 * 256)  qkv_w = (const float*)d_in[i];
        else if (s == 256 * 256)  proj_w = (const float*)d_in[i];
        else if (s == 256)        proj_b = (const float*)d_in[i];
    }
    float* out = (float*)d_out;

    dim3 gTok(1024, 8);
    pool_kernel<<<gTok, 256>>>(x);
    aff_kernel<<<gTok, 256>>>(x);
    fold_kernel<<<gTok, 256>>>();
    gemm_qkv<<<dim3(16, 12, 8), 256>>>(qkv_w);
    attn_kernel<<<dim3(4, 8, 8), 256>>>();
    gemm_proj<<<dim3(16, 4, 8), 256>>>(proj_w, proj_b);
    scatter_kernel<<<dim3(32, 8), 128>>>(out);
}

// round 2
// speedup vs baseline: 1.0242x; 1.0242x over previous
#include <cuda_runtime.h>
#include <math.h>

#define Bv 8
#define Cv 256
#define NW 1024      // 32*32 super tokens
#define NHEADS 8
#define HD 32

// ---------------- scratch (static device memory; no allocs) ----------------
__device__ float g_wf[Bv * NW * Cv];                 // (b, t, c)
__device__ float g_aff[Bv * NW * 16 * 9];            // (b, t, p, i)
__device__ float g_wf2raw[(size_t)Bv * NW * 9 * Cv]; // (b, t, i, c)
__device__ float g_affsumraw[Bv * NW * 9];           // (b, t, i)
__device__ float g_wf2[Bv * NW * Cv];                // (b, t, c)
__device__ float g_qkv[(size_t)Bv * 768 * NW];       // (b, o, n)
__device__ float g_attn_out[(size_t)Bv * Cv * NW];   // (b, c, n)
__device__ float g_proj[(size_t)Bv * NW * Cv];       // (b, n, o)

// ---------------- kernel 1: 4x4 average pool -> wf ----------------
__global__ void pool_kernel(const float* __restrict__ x) {
    int b = blockIdx.y, t = blockIdx.x, c = threadIdx.x;
    int Y = t >> 5, X = t & 31;
    const float* xb = x + (size_t)b * 16384 * 256;
    float s = 0.f;
#pragma unroll
    for (int py = 0; py < 4; py++)
#pragma unroll
        for (int px = 0; px < 4; px++) {
            int n = (Y * 4 + py) * 128 + X * 4 + px;
            s += xb[(size_t)n * 256 + c];
        }
    g_wf[((size_t)b * NW + t) * Cv + c] = s * (1.f / 16.f);
}

// ---------------- kernel 2: affinity softmax + wf2 window partials ----------
__global__ void aff_kernel(const float* __restrict__ x) {
    __shared__ float pix[16][256];
    __shared__ float wfu[9][256];
    __shared__ float lg[16][9];
    __shared__ float affs[16][9];
    int b = blockIdx.y, t = blockIdx.x, tid = threadIdx.x;
    int Y = t >> 5, X = t & 31;
    const float* xb = x + (size_t)b * 16384 * 256;
#pragma unroll
    for (int p = 0; p < 16; p++) {
        int n = (Y * 4 + (p >> 2)) * 128 + X * 4 + (p & 3);
        pix[p][tid] = xb[(size_t)n * 256 + tid];
    }
#pragma unroll
    for (int i = 0; i < 9; i++) {
        int ny = Y + (i / 3) - 1, nx = X + (i % 3) - 1;
        float v = 0.f;
        if ((unsigned)ny < 32u && (unsigned)nx < 32u)
            v = g_wf[((size_t)b * NW + ny * 32 + nx) * Cv + tid];
        wfu[i][tid] = v;
    }
    __syncthreads();
    int warp = tid >> 5, lane = tid & 31;
    for (int pair = warp; pair < 144; pair += 8) {
        int p = pair / 9, i = pair % 9;
        float s = 0.f;
#pragma unroll
        for (int k = 0; k < 8; k++) s += pix[p][lane + 32 * k] * wfu[i][lane + 32 * k];
#pragma unroll
        for (int off = 16; off; off >>= 1) s += __shfl_down_sync(0xffffffffu, s, off);
        if (lane == 0) lg[p][i] = s * 0.0625f;   // scale = C^{-1/2} = 1/16
    }
    __syncthreads();
    if (tid < 16) {
        float m = -1e30f;
#pragma unroll
        for (int i = 0; i < 9; i++) m = fmaxf(m, lg[tid][i]);
        float e[9], sum = 0.f;
#pragma unroll
        for (int i = 0; i < 9; i++) { e[i] = __expf(lg[tid][i] - m); sum += e[i]; }
        float inv = 1.f / sum;
#pragma unroll
        for (int i = 0; i < 9; i++) affs[tid][i] = e[i] * inv;
    }
    __syncthreads();
    if (tid < 144)
        g_aff[((size_t)b * NW + t) * 144 + tid] = affs[tid / 9][tid % 9];
    if (tid >= 160 && tid < 169) {
        int i = tid - 160;
        float s = 0.f;
#pragma unroll
        for (int p = 0; p < 16; p++) s += affs[p][i];
        g_affsumraw[((size_t)b * NW + t) * 9 + i] = s;
    }
    float acc[9];
#pragma unroll
    for (int i = 0; i < 9; i++) acc[i] = 0.f;
#pragma unroll
    for (int p = 0; p < 16; p++) {
        float v = pix[p][tid];
#pragma unroll
        for (int i = 0; i < 9; i++) acc[i] = fmaf(v, affs[p][i], acc[i]);
    }
    size_t base = ((size_t)b * NW + t) * 9 * Cv;
#pragma unroll
    for (int i = 0; i < 9; i++) g_wf2raw[base + (size_t)i * Cv + tid] = acc[i];
}

// ---------------- kernel 3: fold-gather + normalize (float4) ----------------
__global__ void fold_kernel() {
    int b = blockIdx.y;
    int t = blockIdx.x * 4 + (threadIdx.x >> 6);
    int c = (threadIdx.x & 63) * 4;
    int Y = t >> 5, X = t & 31;
    float4 acc = make_float4(0.f, 0.f, 0.f, 0.f);
    float asum = 0.f;
#pragma unroll
    for (int i = 0; i < 9; i++) {
        int ny = Y - ((i / 3) - 1), nx = X - ((i % 3) - 1);
        if ((unsigned)ny < 32u && (unsigned)nx < 32u) {
            size_t nb = (size_t)b * NW + ny * 32 + nx;
            float4 v = *(const float4*)&g_wf2raw[(nb * 9 + i) * Cv + c];
            acc.x += v.x; acc.y += v.y; acc.z += v.z; acc.w += v.w;
            asum += g_affsumraw[nb * 9 + i];
        }
    }
    float inv = 1.f / (asum + 1e-12f);
    acc.x *= inv; acc.y *= inv; acc.z *= inv; acc.w *= inv;
    *(float4*)&g_wf2[((size_t)b * NW + t) * Cv + c] = acc;
}

// ---------------- kernel 4: qkv GEMM (768x1024x256 per batch) ---------------
// A = W (o,k) row-major, B = g_wf2 (n,k) token-major. Both stored k-major in
// smem (transpose on store), read as float4 (conflict-free / broadcast).
__global__ void __launch_bounds__(256) gemm_qkv(const float* __restrict__ W) {
    __shared__ float As[64][68];
    __shared__ float Bs[64][68];
    int b = blockIdx.z;
    int o0 = blockIdx.y * 64, n0 = blockIdx.x * 64;
    int tid = threadIdx.x, tx = tid & 15, ty = tid >> 4;
    float c[4][4] = {};
    const float* Bp = g_wf2 + (size_t)b * NW * Cv;
    for (int k0 = 0; k0 < 256; k0 += 64) {
        __syncthreads();
#pragma unroll
        for (int l = 0; l < 4; l++) {
            int e = tid + l * 256;
            int row = e >> 4, kq = e & 15;
            float4 a4 = *(const float4*)&W[(size_t)(o0 + row) * 256 + k0 + kq * 4];
            As[kq * 4 + 0][row] = a4.x; As[kq * 4 + 1][row] = a4.y;
            As[kq * 4 + 2][row] = a4.z; As[kq * 4 + 3][row] = a4.w;
            float4 b4 = *(const float4*)&Bp[(size_t)(n0 + row) * 256 + k0 + kq * 4];
            Bs[kq * 4 + 0][row] = b4.x; Bs[kq * 4 + 1][row] = b4.y;
            Bs[kq * 4 + 2][row] = b4.z; Bs[kq * 4 + 3][row] = b4.w;
        }
        __syncthreads();
#pragma unroll 16
        for (int k = 0; k < 64; k++) {
            float4 a = *(const float4*)&As[k][ty * 4];
            float4 bb = *(const float4*)&Bs[k][tx * 4];
            c[0][0] = fmaf(a.x, bb.x, c[0][0]); c[0][1] = fmaf(a.x, bb.y, c[0][1]);
            c[0][2] = fmaf(a.x, bb.z, c[0][2]); c[0][3] = fmaf(a.x, bb.w, c[0][3]);
            c[1][0] = fmaf(a.y, bb.x, c[1][0]); c[1][1] = fmaf(a.y, bb.y, c[1][1]);
            c[1][2] = fmaf(a.y, bb.z, c[1][2]); c[1][3] = fmaf(a.y, bb.w, c[1][3]);
            c[2][0] = fmaf(a.z, bb.x, c[2][0]); c[2][1] = fmaf(a.z, bb.y, c[2][1]);
            c[2][2] = fmaf(a.z, bb.z, c[2][2]); c[2][3] = fmaf(a.z, bb.w, c[2][3]);
            c[3][0] = fmaf(a.w, bb.x, c[3][0]); c[3][1] = fmaf(a.w, bb.y, c[3][1]);
            c[3][2] = fmaf(a.w, bb.z, c[3][2]); c[3][3] = fmaf(a.w, bb.w, c[3][3]);
        }
    }
#pragma unroll
    for (int mm = 0; mm < 4; mm++) {
        float4 v = make_float4(c[mm][0], c[mm][1], c[mm][2], c[mm][3]);
        *(float4*)&g_qkv[((size_t)b * 768 + o0 + ty * 4 + mm) * NW + n0 + tx * 4] = v;
    }
}

// ---------------- kernel 5: attention, 2 queries per thread -----------------
__global__ void __launch_bounds__(256, 1) attn_kernel() {
    __shared__ float ks[128][36];
    __shared__ float vs[128][36];
    int b = blockIdx.z, h = blockIdx.y;
    int tid = threadIdx.x;
    int m0 = blockIdx.x * 512 + tid;     // second query: m0 + 256
    const float* qp = g_qkv + ((size_t)b * 768 + h * 96) * NW;
    const float* kp = qp + (size_t)32 * NW;
    const float* vp = qp + (size_t)64 * NW;
    const float hs = 0.17677669529663687f;
    float q0[32], q1[32];
#pragma unroll
    for (int d = 0; d < 32; d++) {
        q0[d] = qp[(size_t)d * NW + m0] * hs;
        q1[d] = qp[(size_t)d * NW + m0 + 256] * hs;
    }
    float mx0 = -INFINITY, mx1 = -INFINITY, l0 = 0.f, l1 = 0.f;
    float a0[32], a1[32];
#pragma unroll
    for (int d = 0; d < 32; d++) { a0[d] = 0.f; a1[d] = 0.f; }
    for (int n0 = 0; n0 < 1024; n0 += 128) {
        __syncthreads();
        for (int e = tid; e < 32 * 128; e += 256) {
            int d = e >> 7, n = e & 127;
            ks[n][d] = kp[(size_t)d * NW + n0 + n];
            vs[n][d] = vp[(size_t)d * NW + n0 + n];
        }
        __syncthreads();
#pragma unroll 2
        for (int n = 0; n < 128; n++) {
            float s0 = 0.f, s1 = 0.f;
#pragma unroll
            for (int d4 = 0; d4 < 8; d4++) {
                float4 kk = *(const float4*)&ks[n][d4 * 4];
                s0 = fmaf(q0[d4 * 4 + 0], kk.x, s0);
                s0 = fmaf(q0[d4 * 4 + 1], kk.y, s0);
                s0 = fmaf(q0[d4 * 4 + 2], kk.z, s0);
                s0 = fmaf(q0[d4 * 4 + 3], kk.w, s0);
                s1 = fmaf(q1[d4 * 4 + 0], kk.x, s1);
                s1 = fmaf(q1[d4 * 4 + 1], kk.y, s1);
                s1 = fmaf(q1[d4 * 4 + 2], kk.z, s1);
                s1 = fmaf(q1[d4 * 4 + 3], kk.w, s1);
            }
            float p0, p1;
            if (s0 > mx0) {
                float corr = __expf(mx0 - s0);
                mx0 = s0; l0 *= corr;
#pragma unroll
                for (int d = 0; d < 32; d++) a0[d] *= corr;
                p0 = 1.f;
            } else p0 = __expf(s0 - mx0);
            if (s1 > mx1) {
                float corr = __expf(mx1 - s1);
                mx1 = s1; l1 *= corr;
#pragma unroll
                for (int d = 0; d < 32; d++) a1[d] *= corr;
                p1 = 1.f;
            } else p1 = __expf(s1 - mx1);
            l0 += p0; l1 += p1;
#pragma unroll
            for (int d4 = 0; d4 < 8; d4++) {
                float4 vv = *(const float4*)&vs[n][d4 * 4];
                a0[d4 * 4 + 0] = fmaf(p0, vv.x, a0[d4 * 4 + 0]);
                a0[d4 * 4 + 1] = fmaf(p0, vv.y, a0[d4 * 4 + 1]);
                a0[d4 * 4 + 2] = fmaf(p0, vv.z, a0[d4 * 4 + 2]);
                a0[d4 * 4 + 3] = fmaf(p0, vv.w, a0[d4 * 4 + 3]);
                a1[d4 * 4 + 0] = fmaf(p1, vv.x, a1[d4 * 4 + 0]);
                a1[d4 * 4 + 1] = fmaf(p1, vv.y, a1[d4 * 4 + 1]);
                a1[d4 * 4 + 2] = fmaf(p1, vv.z, a1[d4 * 4 + 2]);
                a1[d4 * 4 + 3] = fmaf(p1, vv.w, a1[d4 * 4 + 3]);
            }
        }
    }
    float i0 = 1.f / l0, i1 = 1.f / l1;
    float* op = g_attn_out + ((size_t)b * Cv + h * 32) * NW + m0;
#pragma unroll
    for (int d = 0; d < 32; d++) {
        op[(size_t)d * NW] = a0[d] * i0;
        op[(size_t)d * NW + 256] = a1[d] * i1;
    }
}

// ---------------- kernel 6: proj GEMM (+bias), output token-major -----------
__global__ void __launch_bounds__(256) gemm_proj(const float* __restrict__ Wp,
                                                 const float* __restrict__ bias) {
    __shared__ float sm[2 * 64 * 68];
    float (*As)[68] = (float(*)[68])sm;
    float (*Bs)[68] = (float(*)[68])(sm + 64 * 68);
    int b = blockIdx.z, o0 = blockIdx.y * 64, n0 = blockIdx.x * 64;
    int tid = threadIdx.x, tx = tid & 15, ty = tid >> 4;
    float c[4][4] = {};
    const float* Bg = g_attn_out + (size_t)b * Cv * NW;
    for (int k0 = 0; k0 < 256; k0 += 64) {
        __syncthreads();
#pragma unroll
        for (int l = 0; l < 4; l++) {
            int e = tid + l * 256;
            int row = e >> 4, q4 = e & 15;
            float4 a4 = *(const float4*)&Wp[(size_t)(o0 + row) * 256 + k0 + q4 * 4];
            As[q4 * 4 + 0][row] = a4.x; As[q4 * 4 + 1][row] = a4.y;
            As[q4 * 4 + 2][row] = a4.z; As[q4 * 4 + 3][row] = a4.w;
            // B is (k, n): direct float4 store, k-major rows
            float4 b4 = *(const float4*)&Bg[(size_t)(k0 + row) * NW + n0 + q4 * 4];
            *(float4*)&Bs[row][q4 * 4] = b4;
        }
        __syncthreads();
#pragma unroll 16
        for (int k = 0; k < 64; k++) {
            float4 a = *(const float4*)&As[k][ty * 4];
            float4 bb = *(const float4*)&Bs[k][tx * 4];
            c[0][0] = fmaf(a.x, bb.x, c[0][0]); c[0][1] = fmaf(a.x, bb.y, c[0][1]);
            c[0][2] = fmaf(a.x, bb.z, c[0][2]); c[0][3] = fmaf(a.x, bb.w, c[0][3]);
            c[1][0] = fmaf(a.y, bb.x, c[1][0]); c[1][1] = fmaf(a.y, bb.y, c[1][1]);
            c[1][2] = fmaf(a.y, bb.z, c[1][2]); c[1][3] = fmaf(a.y, bb.w, c[1][3]);
            c[2][0] = fmaf(a.z, bb.x, c[2][0]); c[2][1] = fmaf(a.z, bb.y, c[2][1]);
            c[2][2] = fmaf(a.z, bb.z, c[2][2]); c[2][3] = fmaf(a.z, bb.w, c[2][3]);
            c[3][0] = fmaf(a.w, bb.x, c[3][0]); c[3][1] = fmaf(a.w, bb.y, c[3][1]);
            c[3][2] = fmaf(a.w, bb.z, c[3][2]); c[3][3] = fmaf(a.w, bb.w, c[3][3]);
        }
    }
    __syncthreads();
    float* Cs = sm;   // reuse as [n][o] with stride 65
#pragma unroll
    for (int mm = 0; mm < 4; mm++)
#pragma unroll
        for (int nn = 0; nn < 4; nn++)
            Cs[(tx * 4 + nn) * 65 + ty * 4 + mm] = c[mm][nn];
    __syncthreads();
#pragma unroll
    for (int l = 0; l < 16; l++) {
        int e = tid + l * 256;
        int nl = e >> 6, ol = e & 63;
        g_proj[((size_t)b * NW + n0 + nl) * Cv + o0 + ol] = Cs[nl * 65 + ol] + bias[o0 + ol];
    }
}

// ---------------- kernel 7: scatter back to pixels, planar output -----------
__global__ void scatter_kernel(float* __restrict__ out) {
    __shared__ float aff_s[32 * 144];
    __shared__ float r_s[3 * 34 * 33];
    int Y = blockIdx.x, b = blockIdx.y;
    int tid = threadIdx.x;               // 128 threads = w in [0,128)
    int X = tid >> 2, px = tid & 3;
    const float* ab = g_aff + ((size_t)b * NW + Y * 32) * 144;
    for (int idx = tid; idx < 4608; idx += 128) aff_s[idx] = ab[idx];
    for (int idx = tid; idx < 3 * 34 * 33; idx += 128) r_s[idx] = 0.f;
    __syncthreads();
    float a[4][9];
#pragma unroll
    for (int py = 0; py < 4; py++)
#pragma unroll
        for (int i = 0; i < 9; i++)
            a[py][i] = aff_s[X * 144 + (py * 4 + px) * 9 + i];

    for (int c0 = 0; c0 < 256; c0 += 32) {
        __syncthreads();
        for (int idx = tid; idx < 3 * 32 * 32; idx += 128) {
            int dy = idx >> 10;
            int rem = idx & 1023;
            int Xl = rem >> 5, cc = rem & 31;
            int ny = Y + dy - 1;
            if ((unsigned)ny < 32u)
                r_s[((dy * 34) + Xl + 1) * 33 + cc] =
                    g_proj[((size_t)b * NW + ny * 32 + Xl) * Cv + c0 + cc];
        }
        __syncthreads();
#pragma unroll
        for (int py = 0; py < 4; py++) {
            size_t obase = ((size_t)b * 256 + c0) * 16384 +
                           (size_t)(Y * 4 + py) * 128 + tid;
#pragma unroll 4
            for (int c = 0; c < 32; c++) {
                float v = 0.f;
#pragma unroll
                for (int i = 0; i < 9; i++) {
                    int dy = i / 3, dx = i % 3;
                    v = fmaf(r_s[((dy * 34) + X + dx) * 33 + c], a[py][i], v);
                }
                out[obase + (size_t)c * 16384] = v;
            }
        }
    }
}

// ---------------- launch ----------------
extern "C" void kernel_launch(void* const* d_in, const int* in_sizes, int n_in,
                              void* d_out, int out_size) {
    const float* x = nullptr; const float* qkv_w = nullptr;
    const float* proj_w = nullptr; const float* proj_b = nullptr;
    for (int i = 0; i < n_in; i++) {
        int s = in_sizes[i];
        if (s == 8 * 16384 * 256) x = (const float*)d_in[i];
        else if (s == 768 * 256)  qkv_w = (const float*)d_in[i];
        else if (s == 256 * 256)  proj_w = (const float*)d_in[i];
        else if (s == 256)        proj_b = (const float*)d_in[i];
    }
    float* out = (float*)d_out;

    dim3 gTok(1024, 8);
    pool_kernel<<<gTok, 256>>>(x);
    aff_kernel<<<gTok, 256>>>(x);
    fold_kernel<<<dim3(256, 8), 256>>>();
    gemm_qkv<<<dim3(16, 12, 8), 256>>>(qkv_w);
    attn_kernel<<<dim3(2, 8, 8), 256>>>();
    gemm_proj<<<dim3(16, 4, 8), 256>>>(proj_w, proj_b);
    scatter_kernel<<<dim3(32, 8), 128>>>(out);
}

// round 3
// speedup vs baseline: 1.1242x; 1.0977x over previous
#include <cuda_runtime.h>
#include <math.h>

#define Bv 8
#define Cv 256
#define NW 1024      // 32*32 super tokens
#define NHEADS 8
#define HD 32

// ---------------- scratch (static device memory; no allocs) ----------------
__device__ float g_wf[Bv * NW * Cv];                 // (b, t, c)
__device__ float g_aff[Bv * NW * 16 * 9];            // (b, t, p, i)
__device__ float g_wf2raw[(size_t)Bv * NW * 9 * Cv]; // (b, t, i, c)
__device__ float g_affsumraw[Bv * NW * 9];           // (b, t, i)
__device__ float g_wf2[Bv * NW * Cv];                // (b, t, c)
__device__ float g_qkv[(size_t)Bv * 768 * NW];       // (b, o, n)
__device__ float g_attn_out[(size_t)Bv * Cv * NW];   // (b, c, n)
__device__ float g_proj[(size_t)Bv * NW * Cv];       // (b, n, o)

// ---------------- f32x2 packed-math helpers (sm_103a) ----------------
typedef unsigned long long u64;
__device__ __forceinline__ u64 f2_dup(float a) {
    u64 d; asm("mov.b64 %0, {%1, %1};" : "=l"(d) : "f"(a)); return d;
}
__device__ __forceinline__ u64 f2_pack(float a, float b) {
    u64 d; asm("mov.b64 %0, {%1, %2};" : "=l"(d) : "f"(a), "f"(b)); return d;
}
__device__ __forceinline__ void f2_unpack(float& a, float& b, u64 d) {
    asm("mov.b64 {%0, %1}, %2;" : "=f"(a), "=f"(b) : "l"(d));
}
__device__ __forceinline__ void fma2(u64& c, u64 a, u64 b) {
    asm("fma.rn.f32x2 %0, %1, %2, %0;" : "+l"(c) : "l"(a), "l"(b));
}
__device__ __forceinline__ u64 add2(u64 a, u64 b) {
    u64 d; asm("add.rn.f32x2 %0, %1, %2;" : "=l"(d) : "l"(a), "l"(b)); return d;
}
__device__ __forceinline__ void lds128_u64(u64& lo, u64& hi, unsigned saddr) {
    asm volatile("ld.shared.v2.u64 {%0, %1}, [%2];" : "=l"(lo), "=l"(hi) : "r"(saddr));
}
__device__ __forceinline__ unsigned smem_u32(const void* p) {
    unsigned a;
    asm("{ .reg .u64 t; cvta.to.shared.u64 t, %1; cvt.u32.u64 %0, t; }" : "=r"(a) : "l"(p));
    return a;
}

// ---------------- kernel 1: 4x4 average pool -> wf ----------------
__global__ void pool_kernel(const float* __restrict__ x) {
    int b = blockIdx.y, t = blockIdx.x, c = threadIdx.x;
    int Y = t >> 5, X = t & 31;
    const float* xb = x + (size_t)b * 16384 * 256;
    float s = 0.f;
#pragma unroll
    for (int py = 0; py < 4; py++)
#pragma unroll
        for (int px = 0; px < 4; px++) {
            int n = (Y * 4 + py) * 128 + X * 4 + px;
            s += xb[(size_t)n * 256 + c];
        }
    g_wf[((size_t)b * NW + t) * Cv + c] = s * (1.f / 16.f);
}

// ---------------- kernel 2: affinity softmax + wf2 window partials ----------
__global__ void aff_kernel(const float* __restrict__ x) {
    __shared__ float pix[16][256];
    __shared__ float wfu[9][256];
    __shared__ float lg[16][9];
    __shared__ float affs[16][9];
    int b = blockIdx.y, t = blockIdx.x, tid = threadIdx.x;
    int Y = t >> 5, X = t & 31;
    const float* xb = x + (size_t)b * 16384 * 256;
#pragma unroll
    for (int p = 0; p < 16; p++) {
        int n = (Y * 4 + (p >> 2)) * 128 + X * 4 + (p & 3);
        pix[p][tid] = xb[(size_t)n * 256 + tid];
    }
#pragma unroll
    for (int i = 0; i < 9; i++) {
        int ny = Y + (i / 3) - 1, nx = X + (i % 3) - 1;
        float v = 0.f;
        if ((unsigned)ny < 32u && (unsigned)nx < 32u)
            v = g_wf[((size_t)b * NW + ny * 32 + nx) * Cv + tid];
        wfu[i][tid] = v;
    }
    __syncthreads();
    int warp = tid >> 5, lane = tid & 31;
    for (int pair = warp; pair < 144; pair += 8) {
        int p = pair / 9, i = pair % 9;
        float s = 0.f;
#pragma unroll
        for (int k = 0; k < 8; k++) s += pix[p][lane + 32 * k] * wfu[i][lane + 32 * k];
#pragma unroll
        for (int off = 16; off; off >>= 1) s += __shfl_down_sync(0xffffffffu, s, off);
        if (lane == 0) lg[p][i] = s * 0.0625f;
    }
    __syncthreads();
    if (tid < 16) {
        float m = -1e30f;
#pragma unroll
        for (int i = 0; i < 9; i++) m = fmaxf(m, lg[tid][i]);
        float e[9], sum = 0.f;
#pragma unroll
        for (int i = 0; i < 9; i++) { e[i] = __expf(lg[tid][i] - m); sum += e[i]; }
        float inv = 1.f / sum;
#pragma unroll
        for (int i = 0; i < 9; i++) affs[tid][i] = e[i] * inv;
    }
    __syncthreads();
    if (tid < 144)
        g_aff[((size_t)b * NW + t) * 144 + tid] = affs[tid / 9][tid % 9];
    if (tid >= 160 && tid < 169) {
        int i = tid - 160;
        float s = 0.f;
#pragma unroll
        for (int p = 0; p < 16; p++) s += affs[p][i];
        g_affsumraw[((size_t)b * NW + t) * 9 + i] = s;
    }
    float acc[9];
#pragma unroll
    for (int i = 0; i < 9; i++) acc[i] = 0.f;
#pragma unroll
    for (int p = 0; p < 16; p++) {
        float v = pix[p][tid];
#pragma unroll
        for (int i = 0; i < 9; i++) acc[i] = fmaf(v, affs[p][i], acc[i]);
    }
    size_t base = ((size_t)b * NW + t) * 9 * Cv;
#pragma unroll
    for (int i = 0; i < 9; i++) g_wf2raw[base + (size_t)i * Cv + tid] = acc[i];
}

// ---------------- kernel 3: fold-gather + normalize (float4) ----------------
__global__ void fold_kernel() {
    int b = blockIdx.y;
    int t = blockIdx.x * 4 + (threadIdx.x >> 6);
    int c = (threadIdx.x & 63) * 4;
    int Y = t >> 5, X = t & 31;
    float4 acc = make_float4(0.f, 0.f, 0.f, 0.f);
    float asum = 0.f;
#pragma unroll
    for (int i = 0; i < 9; i++) {
        int ny = Y - ((i / 3) - 1), nx = X - ((i % 3) - 1);
        if ((unsigned)ny < 32u && (unsigned)nx < 32u) {
            size_t nb = (size_t)b * NW + ny * 32 + nx;
            float4 v = *(const float4*)&g_wf2raw[(nb * 9 + i) * Cv + c];
            acc.x += v.x; acc.y += v.y; acc.z += v.z; acc.w += v.w;
            asum += g_affsumraw[nb * 9 + i];
        }
    }
    float inv = 1.f / (asum + 1e-12f);
    acc.x *= inv; acc.y *= inv; acc.z *= inv; acc.w *= inv;
    *(float4*)&g_wf2[((size_t)b * NW + t) * Cv + c] = acc;
}

// ---------------- kernel 4: qkv GEMM 128x128 tile, 8x8/thread, f32x2 --------
// A = W (o,k) row-major; B = g_wf2 (n,k) row-major. Both transposed to
// k-major in smem. Output g_qkv (o, n).
__global__ void __launch_bounds__(256, 2) gemm_qkv(const float* __restrict__ W) {
    __shared__ __align__(16) float As[32][132];
    __shared__ __align__(16) float Bs[32][132];
    int b = blockIdx.z;
    int o0 = blockIdx.y * 128, n0 = blockIdx.x * 128;
    int tid = threadIdx.x, tx = tid & 15, ty = tid >> 4;
    const float* Bp = g_wf2 + (size_t)b * NW * Cv;
    u64 acc[8][4];
#pragma unroll
    for (int m = 0; m < 8; m++)
#pragma unroll
        for (int n = 0; n < 4; n++) acc[m][n] = 0ull;
    unsigned bs_base = smem_u32(&Bs[0][0]) + tx * 32;   // Bs[k][tx*8]
    int lr = tid >> 1, lc = (tid & 1) * 4;              // load row / col4-base
    for (int k0 = 0; k0 < 256; k0 += 32) {
        __syncthreads();
#pragma unroll
        for (int i = 0; i < 4; i++) {
            float4 a4 = *(const float4*)&W[(size_t)(o0 + lr) * 256 + k0 + (lc + i) * 4];
            As[(lc + i) * 4 + 0][lr] = a4.x; As[(lc + i) * 4 + 1][lr] = a4.y;
            As[(lc + i) * 4 + 2][lr] = a4.z; As[(lc + i) * 4 + 3][lr] = a4.w;
            float4 b4 = *(const float4*)&Bp[(size_t)(n0 + lr) * 256 + k0 + (lc + i) * 4];
            Bs[(lc + i) * 4 + 0][lr] = b4.x; Bs[(lc + i) * 4 + 1][lr] = b4.y;
            Bs[(lc + i) * 4 + 2][lr] = b4.z; Bs[(lc + i) * 4 + 3][lr] = b4.w;
        }
        __syncthreads();
#pragma unroll 8
        for (int k = 0; k < 32; k++) {
            float4 a0 = *(const float4*)&As[k][ty * 8];
            float4 a1 = *(const float4*)&As[k][ty * 8 + 4];
            u64 b0, b1, b2, b3;
            lds128_u64(b0, b1, bs_base + k * 528);
            lds128_u64(b2, b3, bs_base + k * 528 + 16);
            float am[8] = {a0.x, a0.y, a0.z, a0.w, a1.x, a1.y, a1.z, a1.w};
#pragma unroll
            for (int m = 0; m < 8; m++) {
                u64 ad = f2_dup(am[m]);
                fma2(acc[m][0], ad, b0); fma2(acc[m][1], ad, b1);
                fma2(acc[m][2], ad, b2); fma2(acc[m][3], ad, b3);
            }
        }
    }
#pragma unroll
    for (int m = 0; m < 8; m++) {
        float f[8];
#pragma unroll
        for (int n = 0; n < 4; n++) f2_unpack(f[2 * n], f[2 * n + 1], acc[m][n]);
        float* dst = &g_qkv[((size_t)b * 768 + o0 + ty * 8 + m) * NW + n0 + tx * 8];
        *(float4*)dst = make_float4(f[0], f[1], f[2], f[3]);
        *(float4*)(dst + 4) = make_float4(f[4], f[5], f[6], f[7]);
    }
}

// ---------------- kernel 5: attention, 1 q/thread, f32x2, branch-free -------
__global__ void __launch_bounds__(256, 2) attn_kernel() {
    __shared__ __align__(16) float ks[128][36];
    __shared__ __align__(16) float vs[128][36];
    int b = blockIdx.z, h = blockIdx.y;
    int tid = threadIdx.x;
    int m = blockIdx.x * 256 + tid;
    const float* qp = g_qkv + ((size_t)b * 768 + h * 96) * NW;
    const float* kp = qp + (size_t)32 * NW;
    const float* vp = qp + (size_t)64 * NW;
    const float hs = 0.17677669529663687f;
    u64 q2[16], a2[16];
#pragma unroll
    for (int i = 0; i < 16; i++) {
        q2[i] = f2_pack(qp[(size_t)(2 * i) * NW + m] * hs,
                        qp[(size_t)(2 * i + 1) * NW + m] * hs);
        a2[i] = 0ull;
    }
    float l = 0.f;
    unsigned ks_base = smem_u32(&ks[0][0]);
    unsigned vs_base = smem_u32(&vs[0][0]);
    for (int n0 = 0; n0 < 1024; n0 += 128) {
        __syncthreads();
        for (int e = tid; e < 32 * 128; e += 256) {
            int d = e >> 7, n = e & 127;
            ks[n][d] = kp[(size_t)d * NW + n0 + n];
            vs[n][d] = vp[(size_t)d * NW + n0 + n];
        }
        __syncthreads();
#pragma unroll 2
        for (int n = 0; n < 128; n++) {
            unsigned ka = ks_base + n * 144;
            u64 s0 = 0ull, s1 = 0ull, s2 = 0ull, s3 = 0ull;
            u64 klo, khi;
            lds128_u64(klo, khi, ka);       fma2(s0, q2[0], klo);  fma2(s1, q2[1], khi);
            lds128_u64(klo, khi, ka + 16);  fma2(s2, q2[2], klo);  fma2(s3, q2[3], khi);
            lds128_u64(klo, khi, ka + 32);  fma2(s0, q2[4], klo);  fma2(s1, q2[5], khi);
            lds128_u64(klo, khi, ka + 48);  fma2(s2, q2[6], klo);  fma2(s3, q2[7], khi);
            lds128_u64(klo, khi, ka + 64);  fma2(s0, q2[8], klo);  fma2(s1, q2[9], khi);
            lds128_u64(klo, khi, ka + 80);  fma2(s2, q2[10], klo); fma2(s3, q2[11], khi);
            lds128_u64(klo, khi, ka + 96);  fma2(s0, q2[12], klo); fma2(s1, q2[13], khi);
            lds128_u64(klo, khi, ka + 112); fma2(s2, q2[14], klo); fma2(s3, q2[15], khi);
            u64 st = add2(add2(s0, s1), add2(s2, s3));
            float sx, sy;
            f2_unpack(sx, sy, st);
            float p = __expf(sx + sy);
            l += p;
            u64 p2 = f2_dup(p);
            unsigned va = vs_base + n * 144;
            u64 v0, v1;
#pragma unroll
            for (int i = 0; i < 8; i++) {
                lds128_u64(v0, v1, va + 16 * i);
                fma2(a2[2 * i], p2, v0);
                fma2(a2[2 * i + 1], p2, v1);
            }
        }
    }
    float inv = 1.f / l;
    float* op = g_attn_out + ((size_t)b * Cv + h * 32) * NW + m;
#pragma unroll
    for (int i = 0; i < 16; i++) {
        float x, y;
        f2_unpack(x, y, a2[i]);
        op[(size_t)(2 * i) * NW] = x * inv;
        op[(size_t)(2 * i + 1) * NW] = y * inv;
    }
}

// ---------------- kernel 6: proj GEMM 128x128 tile, f32x2, +bias ------------
// A = Wp (o,k); B = g_attn_out (k, n) already k-major. Output g_proj (n, o).
__global__ void __launch_bounds__(256, 2) gemm_proj(const float* __restrict__ Wp,
                                                    const float* __restrict__ bias) {
    __shared__ __align__(16) float As[32][132];
    __shared__ __align__(16) float Bs[32][132];
    int b = blockIdx.z, o0 = blockIdx.y * 128, n0 = blockIdx.x * 128;
    int tid = threadIdx.x, tx = tid & 15, ty = tid >> 4;
    const float* Bg = g_attn_out + (size_t)b * Cv * NW;
    u64 acc[8][4];
#pragma unroll
    for (int m = 0; m < 8; m++)
#pragma unroll
        for (int n = 0; n < 4; n++) acc[m][n] = 0ull;
    unsigned bs_base = smem_u32(&Bs[0][0]) + tx * 32;
    int lr = tid >> 1, lc = (tid & 1) * 4;          // A loader (transpose)
    int bkk = tid >> 3, bj = tid & 7;               // B loader (direct)
    for (int k0 = 0; k0 < 256; k0 += 32) {
        __syncthreads();
#pragma unroll
        for (int i = 0; i < 4; i++) {
            float4 a4 = *(const float4*)&Wp[(size_t)(o0 + lr) * 256 + k0 + (lc + i) * 4];
            As[(lc + i) * 4 + 0][lr] = a4.x; As[(lc + i) * 4 + 1][lr] = a4.y;
            As[(lc + i) * 4 + 2][lr] = a4.z; As[(lc + i) * 4 + 3][lr] = a4.w;
            float4 b4 = *(const float4*)&Bg[(size_t)(k0 + bkk) * NW + n0 + (bj + i * 8) * 4];
            *(float4*)&Bs[bkk][(bj + i * 8) * 4] = b4;
        }
        __syncthreads();
#pragma unroll 8
        for (int k = 0; k < 32; k++) {
            float4 a0 = *(const float4*)&As[k][ty * 8];
            float4 a1 = *(const float4*)&As[k][ty * 8 + 4];
            u64 b0, b1, b2, b3;
            lds128_u64(b0, b1, bs_base + k * 528);
            lds128_u64(b2, b3, bs_base + k * 528 + 16);
            float am[8] = {a0.x, a0.y, a0.z, a0.w, a1.x, a1.y, a1.z, a1.w};
#pragma unroll
            for (int m = 0; m < 8; m++) {
                u64 ad = f2_dup(am[m]);
                fma2(acc[m][0], ad, b0); fma2(acc[m][1], ad, b1);
                fma2(acc[m][2], ad, b2); fma2(acc[m][3], ad, b3);
            }
        }
    }
    float f[8][8];
#pragma unroll
    for (int m = 0; m < 8; m++)
#pragma unroll
        for (int n = 0; n < 4; n++) f2_unpack(f[m][2 * n], f[m][2 * n + 1], acc[m][n]);
    float bb[8];
#pragma unroll
    for (int m = 0; m < 8; m++) bb[m] = bias[o0 + ty * 8 + m];
#pragma unroll
    for (int nn = 0; nn < 8; nn++) {
        float* dst = &g_proj[((size_t)b * NW + n0 + tx * 8 + nn) * Cv + o0 + ty * 8];
        *(float4*)dst = make_float4(f[0][nn] + bb[0], f[1][nn] + bb[1],
                                    f[2][nn] + bb[2], f[3][nn] + bb[3]);
        *(float4*)(dst + 4) = make_float4(f[4][nn] + bb[4], f[5][nn] + bb[5],
                                          f[6][nn] + bb[6], f[7][nn] + bb[7]);
    }
}

// ---------------- kernel 7: scatter back to pixels, planar output -----------
__global__ void scatter_kernel(float* __restrict__ out) {
    __shared__ float aff_s[32 * 144];
    __shared__ float r_s[3 * 34 * 33];
    int Y = blockIdx.x, b = blockIdx.y;
    int tid = threadIdx.x;
    int X = tid >> 2, px = tid & 3;
    const float* ab = g_aff + ((size_t)b * NW + Y * 32) * 144;
    for (int idx = tid; idx < 4608; idx += 128) aff_s[idx] = ab[idx];
    for (int idx = tid; idx < 3 * 34 * 33; idx += 128) r_s[idx] = 0.f;
    __syncthreads();
    float a[4][9];
#pragma unroll
    for (int py = 0; py < 4; py++)
#pragma unroll
        for (int i = 0; i < 9; i++)
            a[py][i] = aff_s[X * 144 + (py * 4 + px) * 9 + i];

    for (int c0 = 0; c0 < 256; c0 += 32) {
        __syncthreads();
        for (int idx = tid; idx < 3 * 32 * 32; idx += 128) {
            int dy = idx >> 10;
            int rem = idx & 1023;
            int Xl = rem >> 5, cc = rem & 31;
            int ny = Y + dy - 1;
            if ((unsigned)ny < 32u)
                r_s[((dy * 34) + Xl + 1) * 33 + cc] =
                    g_proj[((size_t)b * NW + ny * 32 + Xl) * Cv + c0 + cc];
        }
        __syncthreads();
#pragma unroll
        for (int py = 0; py < 4; py++) {
            size_t obase = ((size_t)b * 256 + c0) * 16384 +
                           (size_t)(Y * 4 + py) * 128 + tid;
#pragma unroll 4
            for (int c = 0; c < 32; c++) {
                float v = 0.f;
#pragma unroll
                for (int i = 0; i < 9; i++) {
                    int dy = i / 3, dx = i % 3;
                    v = fmaf(r_s[((dy * 34) + X + dx) * 33 + c], a[py][i], v);
                }
                out[obase + (size_t)c * 16384] = v;
            }
        }
    }
}

// ---------------- launch ----------------
extern "C" void kernel_launch(void* const* d_in, const int* in_sizes, int n_in,
                              void* d_out, int out_size) {
    const float* x = nullptr; const float* qkv_w = nullptr;
    const float* proj_w = nullptr; const float* proj_b = nullptr;
    for (int i = 0; i < n_in; i++) {
        int s = in_sizes[i];
        if (s == 8 * 16384 * 256) x = (const float*)d_in[i];
        else if (s == 768 * 256)  qkv_w = (const float*)d_in[i];
        else if (s == 256 * 256)  proj_w = (const float*)d_in[i];
        else if (s == 256)        proj_b = (const float*)d_in[i];
    }
    float* out = (float*)d_out;

    dim3 gTok(1024, 8);
    pool_kernel<<<gTok, 256>>>(x);
    aff_kernel<<<gTok, 256>>>(x);
    fold_kernel<<<dim3(256, 8), 256>>>();
    gemm_qkv<<<dim3(8, 6, 8), 256>>>(qkv_w);
    attn_kernel<<<dim3(4, 8, 8), 256>>>();
    gemm_proj<<<dim3(8, 2, 8), 256>>>(proj_w, proj_b);
    scatter_kernel<<<dim3(32, 8), 128>>>(out);
}

// round 5
// speedup vs baseline: 1.1496x; 1.0225x over previous
#include <cuda_runtime.h>
#include <math.h>

#define Bv 8
#define Cv 256
#define NW 1024      // 32*32 super tokens
#define NHEADS 8
#define HD 32

// ---------------- scratch (static device memory; no allocs) ----------------
__device__ float g_wf[Bv * NW * Cv];                 // (b, t, c)
__device__ float g_aff[Bv * NW * 16 * 9];            // (b, t, p, i)
__device__ float g_wf2raw[(size_t)Bv * NW * 9 * Cv]; // (b, t, i, c)
__device__ float g_affsumraw[Bv * NW * 9];           // (b, t, i)
__device__ float g_wf2[Bv * NW * Cv];                // (b, t, c)
__device__ float g_qkv[(size_t)Bv * 768 * NW];       // (b, o, n)
__device__ float g_attn_out[(size_t)Bv * Cv * NW];   // (b, c, n)
__device__ float g_proj[(size_t)Bv * NW * Cv];       // (b, n, o)

// ---------------- f32x2 packed-math helpers (sm_103a) ----------------
typedef unsigned long long u64;
__device__ __forceinline__ u64 f2_dup(float a) {
    u64 d; asm("mov.b64 %0, {%1, %1};" : "=l"(d) : "f"(a)); return d;
}
__device__ __forceinline__ u64 f2_pack(float a, float b) {
    u64 d; asm("mov.b64 %0, {%1, %2};" : "=l"(d) : "f"(a), "f"(b)); return d;
}
__device__ __forceinline__ void f2_unpack(float& a, float& b, u64 d) {
    asm("mov.b64 {%0, %1}, %2;" : "=f"(a), "=f"(b) : "l"(d));
}
__device__ __forceinline__ void fma2(u64& c, u64 a, u64 b) {
    asm("fma.rn.f32x2 %0, %1, %2, %0;" : "+l"(c) : "l"(a), "l"(b));
}
__device__ __forceinline__ u64 add2(u64 a, u64 b) {
    u64 d; asm("add.rn.f32x2 %0, %1, %2;" : "=l"(d) : "l"(a), "l"(b)); return d;
}
__device__ __forceinline__ void lds128_u64(u64& lo, u64& hi, unsigned saddr) {
    asm volatile("ld.shared.v2.u64 {%0, %1}, [%2];" : "=l"(lo), "=l"(hi) : "r"(saddr));
}
__device__ __forceinline__ unsigned smem_u32(const void* p) {
    unsigned a;
    asm("{ .reg .u64 t; cvta.to.shared.u64 t, %1; cvt.u32.u64 %0, t; }" : "=r"(a) : "l"(p));
    return a;
}

// ---------------- kernel 1: 4x4 average pool -> wf (float4) ----------------
__global__ void pool_kernel(const float* __restrict__ x) {
    int b = blockIdx.y;
    int t = blockIdx.x * 4 + (threadIdx.x >> 6);
    int c4 = (threadIdx.x & 63) * 4;
    int Y = t >> 5, X = t & 31;
    const float* xb = x + (size_t)b * 16384 * 256;
    float4 s = make_float4(0.f, 0.f, 0.f, 0.f);
#pragma unroll
    for (int py = 0; py < 4; py++)
#pragma unroll
        for (int px = 0; px < 4; px++) {
            int n = (Y * 4 + py) * 128 + X * 4 + px;
            float4 v = *(const float4*)&xb[(size_t)n * 256 + c4];
            s.x += v.x; s.y += v.y; s.z += v.z; s.w += v.w;
        }
    s.x *= (1.f / 16.f); s.y *= (1.f / 16.f); s.z *= (1.f / 16.f); s.w *= (1.f / 16.f);
    *(float4*)&g_wf[((size_t)b * NW + t) * Cv + c4] = s;
}

// ---------------- kernel 2: affinity softmax + wf2 window partials ----------
__global__ void aff_kernel(const float* __restrict__ x) {
    __shared__ float pix[16][256];
    __shared__ float wfu[9][256];
    __shared__ float lg[16][9];
    __shared__ float affs[16][9];
    int b = blockIdx.y, t = blockIdx.x, tid = threadIdx.x;
    int Y = t >> 5, X = t & 31;
    const float* xb = x + (size_t)b * 16384 * 256;
    {
        int c4 = (tid & 63) * 4;
#pragma unroll
        for (int pp = 0; pp < 4; pp++) {
            int p = pp * 4 + (tid >> 6);
            int n = (Y * 4 + (p >> 2)) * 128 + X * 4 + (p & 3);
            *(float4*)&pix[p][c4] = *(const float4*)&xb[(size_t)n * 256 + c4];
        }
#pragma unroll
        for (int ii = 0; ii < 3; ii++) {
            int i = ii * 4 + (tid >> 6);
            if (i < 9) {
                int ny = Y + (i / 3) - 1, nx = X + (i % 3) - 1;
                float4 v = make_float4(0.f, 0.f, 0.f, 0.f);
                if ((unsigned)ny < 32u && (unsigned)nx < 32u)
                    v = *(const float4*)&g_wf[((size_t)b * NW + ny * 32 + nx) * Cv + c4];
                *(float4*)&wfu[i][c4] = v;
            }
        }
    }
    __syncthreads();
    int warp = tid >> 5, lane = tid & 31;
    for (int pair = warp; pair < 144; pair += 8) {
        int p = pair / 9, i = pair % 9;
        float s = 0.f;
#pragma unroll
        for (int k = 0; k < 8; k++) s += pix[p][lane + 32 * k] * wfu[i][lane + 32 * k];
#pragma unroll
        for (int off = 16; off; off >>= 1) s += __shfl_down_sync(0xffffffffu, s, off);
        if (lane == 0) lg[p][i] = s * 0.0625f;
    }
    __syncthreads();
    if (tid < 16) {
        float m = -1e30f;
#pragma unroll
        for (int i = 0; i < 9; i++) m = fmaxf(m, lg[tid][i]);
        float e[9], sum = 0.f;
#pragma unroll
        for (int i = 0; i < 9; i++) { e[i] = __expf(lg[tid][i] - m); sum += e[i]; }
        float inv = 1.f / sum;
#pragma unroll
        for (int i = 0; i < 9; i++) affs[tid][i] = e[i] * inv;
    }
    __syncthreads();
    if (tid < 144)
        g_aff[((size_t)b * NW + t) * 144 + tid] = affs[tid / 9][tid % 9];
    if (tid >= 160 && tid < 169) {
        int i = tid - 160;
        float s = 0.f;
#pragma unroll
        for (int p = 0; p < 16; p++) s += affs[p][i];
        g_affsumraw[((size_t)b * NW + t) * 9 + i] = s;
    }
    float acc[9];
#pragma unroll
    for (int i = 0; i < 9; i++) acc[i] = 0.f;
#pragma unroll
    for (int p = 0; p < 16; p++) {
        float v = pix[p][tid];
#pragma unroll
        for (int i = 0; i < 9; i++) acc[i] = fmaf(v, affs[p][i], acc[i]);
    }
    size_t base = ((size_t)b * NW + t) * 9 * Cv;
#pragma unroll
    for (int i = 0; i < 9; i++) g_wf2raw[base + (size_t)i * Cv + tid] = acc[i];
}

// ---------------- kernel 3: fold-gather + normalize (float4) ----------------
__global__ void fold_kernel() {
    int b = blockIdx.y;
    int t = blockIdx.x * 4 + (threadIdx.x >> 6);
    int c = (threadIdx.x & 63) * 4;
    int Y = t >> 5, X = t & 31;
    float4 acc = make_float4(0.f, 0.f, 0.f, 0.f);
    float asum = 0.f;
#pragma unroll
    for (int i = 0; i < 9; i++) {
        int ny = Y - ((i / 3) - 1), nx = X - ((i % 3) - 1);
        if ((unsigned)ny < 32u && (unsigned)nx < 32u) {
            size_t nb = (size_t)b * NW + ny * 32 + nx;
            float4 v = *(const float4*)&g_wf2raw[(nb * 9 + i) * Cv + c];
            acc.x += v.x; acc.y += v.y; acc.z += v.z; acc.w += v.w;
            asum += g_affsumraw[nb * 9 + i];
        }
    }
    float inv = 1.f / (asum + 1e-12f);
    acc.x *= inv; acc.y *= inv; acc.z *= inv; acc.w *= inv;
    *(float4*)&g_wf2[((size_t)b * NW + t) * Cv + c] = acc;
}

// ---------------- kernel 4: qkv GEMM, double-buffered, f32x2 ----------------
// A = W (o,k); B = g_wf2 (n,k). Both transposed to k-major in smem.
// k-slice = 16, 2 stages. 128x128 tile, 8x8 per thread.
// Loader: 512 float4 per array per slice; e = tid / tid+256; row=e>>2, kq=e&3.
__global__ void __launch_bounds__(256, 2) gemm_qkv(const float* __restrict__ W) {
    __shared__ __align__(16) float As[2][16][132];
    __shared__ __align__(16) float Bs[2][16][132];
    int b = blockIdx.z;
    int o0 = blockIdx.y * 128, n0 = blockIdx.x * 128;
    int tid = threadIdx.x, tx = tid & 15, ty = tid >> 4;
    const float* Bp = g_wf2 + (size_t)b * NW * Cv;
    u64 acc[8][4];
#pragma unroll
    for (int m = 0; m < 8; m++)
#pragma unroll
        for (int n = 0; n < 4; n++) acc[m][n] = 0ull;
    int r0 = tid >> 2, kq0 = tid & 3;                  // rows 0..63
    int r1 = (tid + 256) >> 2, kq1 = (tid + 256) & 3;  // rows 64..127
    const float* Wr0 = &W[(size_t)(o0 + r0) * 256 + kq0 * 4];
    const float* Wr1 = &W[(size_t)(o0 + r1) * 256 + kq1 * 4];
    const float* Br0 = &Bp[(size_t)(n0 + r0) * 256 + kq0 * 4];
    const float* Br1 = &Bp[(size_t)(n0 + r1) * 256 + kq1 * 4];
    float4 ra0, ra1, rb0, rb1;
    ra0 = *(const float4*)(Wr0); ra1 = *(const float4*)(Wr1);
    rb0 = *(const float4*)(Br0); rb1 = *(const float4*)(Br1);
#define STORE_SLICE(s)                                                         \
    {   As[s][kq0 * 4 + 0][r0] = ra0.x; As[s][kq0 * 4 + 1][r0] = ra0.y;        \
        As[s][kq0 * 4 + 2][r0] = ra0.z; As[s][kq0 * 4 + 3][r0] = ra0.w;        \
        As[s][kq1 * 4 + 0][r1] = ra1.x; As[s][kq1 * 4 + 1][r1] = ra1.y;        \
        As[s][kq1 * 4 + 2][r1] = ra1.z; As[s][kq1 * 4 + 3][r1] = ra1.w;        \
        Bs[s][kq0 * 4 + 0][r0] = rb0.x; Bs[s][kq0 * 4 + 1][r0] = rb0.y;        \
        Bs[s][kq0 * 4 + 2][r0] = rb0.z; Bs[s][kq0 * 4 + 3][r0] = rb0.w;        \
        Bs[s][kq1 * 4 + 0][r1] = rb1.x; Bs[s][kq1 * 4 + 1][r1] = rb1.y;        \
        Bs[s][kq1 * 4 + 2][r1] = rb1.z; Bs[s][kq1 * 4 + 3][r1] = rb1.w; }
    STORE_SLICE(0);
    __syncthreads();
    unsigned bs0 = smem_u32(&Bs[0][0][0]) + tx * 32;
#pragma unroll 1
    for (int i = 0; i < 16; i++) {
        if (i < 15) {
            int k0 = (i + 1) * 16;
            ra0 = *(const float4*)(Wr0 + k0); ra1 = *(const float4*)(Wr1 + k0);
            rb0 = *(const float4*)(Br0 + k0); rb1 = *(const float4*)(Br1 + k0);
        }
        const float(*Asl)[132] = As[i & 1];
        unsigned bsb = bs0 + (i & 1) * (16 * 132 * 4);
#pragma unroll
        for (int k = 0; k < 16; k++) {
            float4 a0 = *(const float4*)&Asl[k][ty * 8];
            float4 a1 = *(const float4*)&Asl[k][ty * 8 + 4];
            u64 b0, b1, b2, b3;
            lds128_u64(b0, b1, bsb + k * 528);
            lds128_u64(b2, b3, bsb + k * 528 + 16);
            float am[8] = {a0.x, a0.y, a0.z, a0.w, a1.x, a1.y, a1.z, a1.w};
#pragma unroll
            for (int m = 0; m < 8; m++) {
                u64 ad = f2_dup(am[m]);
                fma2(acc[m][0], ad, b0); fma2(acc[m][1], ad, b1);
                fma2(acc[m][2], ad, b2); fma2(acc[m][3], ad, b3);
            }
        }
        __syncthreads();
        if (i < 15) {
            STORE_SLICE((i + 1) & 1);
            __syncthreads();
        }
    }
#pragma unroll
    for (int m = 0; m < 8; m++) {
        float f[8];
#pragma unroll
        for (int n = 0; n < 4; n++) f2_unpack(f[2 * n], f[2 * n + 1], acc[m][n]);
        float* dst = &g_qkv[((size_t)b * 768 + o0 + ty * 8 + m) * NW + n0 + tx * 8];
        *(float4*)dst = make_float4(f[0], f[1], f[2], f[3]);
        *(float4*)(dst + 4) = make_float4(f[4], f[5], f[6], f[7]);
    }
#undef STORE_SLICE
}

// ---------------- kernel 5: attention, 1 q/thread, f32x2, n-unroll 2 --------
__global__ void __launch_bounds__(256, 2) attn_kernel() {
    __shared__ __align__(16) float ks[128][36];
    __shared__ __align__(16) float vs[128][36];
    int b = blockIdx.z, h = blockIdx.y;
    int tid = threadIdx.x;
    int m = blockIdx.x * 256 + tid;
    const float* qp = g_qkv + ((size_t)b * 768 + h * 96) * NW;
    const float* kp = qp + (size_t)32 * NW;
    const float* vp = qp + (size_t)64 * NW;
    const float hs = 0.17677669529663687f;
    u64 q2[16], a2[16];
#pragma unroll
    for (int i = 0; i < 16; i++) {
        q2[i] = f2_pack(qp[(size_t)(2 * i) * NW + m] * hs,
                        qp[(size_t)(2 * i + 1) * NW + m] * hs);
        a2[i] = 0ull;
    }
    float l = 0.f;
    unsigned ks_base = smem_u32(&ks[0][0]);
    unsigned vs_base = smem_u32(&vs[0][0]);
    for (int n0 = 0; n0 < 1024; n0 += 128) {
        __syncthreads();
        for (int e = tid; e < 32 * 128; e += 256) {
            int d = e >> 7, n = e & 127;
            ks[n][d] = kp[(size_t)d * NW + n0 + n];
            vs[n][d] = vp[(size_t)d * NW + n0 + n];
        }
        __syncthreads();
#pragma unroll 2
        for (int n = 0; n < 128; n += 2) {
            unsigned ka = ks_base + n * 144;
            u64 sA0 = 0ull, sA1 = 0ull, sB0 = 0ull, sB1 = 0ull;
            u64 klo, khi;
            lds128_u64(klo, khi, ka);       fma2(sA0, q2[0], klo);  fma2(sA1, q2[1], khi);
            lds128_u64(klo, khi, ka + 16);  fma2(sA0, q2[2], klo);  fma2(sA1, q2[3], khi);
            lds128_u64(klo, khi, ka + 32);  fma2(sA0, q2[4], klo);  fma2(sA1, q2[5], khi);
            lds128_u64(klo, khi, ka + 48);  fma2(sA0, q2[6], klo);  fma2(sA1, q2[7], khi);
            lds128_u64(klo, khi, ka + 64);  fma2(sA0, q2[8], klo);  fma2(sA1, q2[9], khi);
            lds128_u64(klo, khi, ka + 80);  fma2(sA0, q2[10], klo); fma2(sA1, q2[11], khi);
            lds128_u64(klo, khi, ka + 96);  fma2(sA0, q2[12], klo); fma2(sA1, q2[13], khi);
            lds128_u64(klo, khi, ka + 112); fma2(sA0, q2[14], klo); fma2(sA1, q2[15], khi);
            lds128_u64(klo, khi, ka + 144);       fma2(sB0, q2[0], klo);  fma2(sB1, q2[1], khi);
            lds128_u64(klo, khi, ka + 144 + 16);  fma2(sB0, q2[2], klo);  fma2(sB1, q2[3], khi);
            lds128_u64(klo, khi, ka + 144 + 32);  fma2(sB0, q2[4], klo);  fma2(sB1, q2[5], khi);
            lds128_u64(klo, khi, ka + 144 + 48);  fma2(sB0, q2[6], klo);  fma2(sB1, q2[7], khi);
            lds128_u64(klo, khi, ka + 144 + 64);  fma2(sB0, q2[8], klo);  fma2(sB1, q2[9], khi);
            lds128_u64(klo, khi, ka + 144 + 80);  fma2(sB0, q2[10], klo); fma2(sB1, q2[11], khi);
            lds128_u64(klo, khi, ka + 144 + 96);  fma2(sB0, q2[12], klo); fma2(sB1, q2[13], khi);
            lds128_u64(klo, khi, ka + 144 + 112); fma2(sB0, q2[14], klo); fma2(sB1, q2[15], khi);
            u64 stA = add2(sA0, sA1);
            u64 stB = add2(sB0, sB1);
            float ax, ay, bx, by;
            f2_unpack(ax, ay, stA);
            f2_unpack(bx, by, stB);
            float pA = __expf(ax + ay);
            float pB = __expf(bx + by);
            l += pA + pB;
            u64 pA2 = f2_dup(pA), pB2 = f2_dup(pB);
            unsigned va = vs_base + n * 144;
            u64 v0, v1;
#pragma unroll
            for (int i = 0; i < 8; i++) {
                lds128_u64(v0, v1, va + 16 * i);
                fma2(a2[2 * i], pA2, v0);
                fma2(a2[2 * i + 1], pA2, v1);
            }
#pragma unroll
            for (int i = 0; i < 8; i++) {
                lds128_u64(v0, v1, va + 144 + 16 * i);
                fma2(a2[2 * i], pB2, v0);
                fma2(a2[2 * i + 1], pB2, v1);
            }
        }
    }
    float inv = 1.f / l;
    float* op = g_attn_out + ((size_t)b * Cv + h * 32) * NW + m;
#pragma unroll
    for (int i = 0; i < 16; i++) {
        float x, y;
        f2_unpack(x, y, a2[i]);
        op[(size_t)(2 * i) * NW] = x * inv;
        op[(size_t)(2 * i + 1) * NW] = y * inv;
    }
}

// ---------------- kernel 6: proj GEMM, double-buffered, f32x2, +bias --------
// A = Wp (o,k) transposed to k-major; B = g_attn_out (k,n) direct.
__global__ void __launch_bounds__(256, 2) gemm_proj(const float* __restrict__ Wp,
                                                    const float* __restrict__ bias) {
    __shared__ __align__(16) float As[2][16][132];
    __shared__ __align__(16) float Bs[2][16][132];
    int b = blockIdx.z, o0 = blockIdx.y * 128, n0 = blockIdx.x * 128;
    int tid = threadIdx.x, tx = tid & 15, ty = tid >> 4;
    const float* Bg = g_attn_out + (size_t)b * Cv * NW;
    u64 acc[8][4];
#pragma unroll
    for (int m = 0; m < 8; m++)
#pragma unroll
        for (int n = 0; n < 4; n++) acc[m][n] = 0ull;
    int r0 = tid >> 2, kq0 = tid & 3;
    int r1 = (tid + 256) >> 2, kq1 = (tid + 256) & 3;
    const float* Wr0 = &Wp[(size_t)(o0 + r0) * 256 + kq0 * 4];
    const float* Wr1 = &Wp[(size_t)(o0 + r1) * 256 + kq1 * 4];
    int bk0 = tid >> 5, bc0 = tid & 31;                 // B loader: 8 k-rows / pass
    int bk1 = bk0 + 8;
    const float* Bg0 = &Bg[(size_t)bk0 * NW + n0 + bc0 * 4];
    const float* Bg1 = &Bg[(size_t)bk1 * NW + n0 + bc0 * 4];
    float4 ra0, ra1, rb0, rb1;
    ra0 = *(const float4*)(Wr0); ra1 = *(const float4*)(Wr1);
    rb0 = *(const float4*)(Bg0); rb1 = *(const float4*)(Bg1);
#define STORE_SLICE_P(s)                                                       \
    {   As[s][kq0 * 4 + 0][r0] = ra0.x; As[s][kq0 * 4 + 1][r0] = ra0.y;        \
        As[s][kq0 * 4 + 2][r0] = ra0.z; As[s][kq0 * 4 + 3][r0] = ra0.w;        \
        As[s][kq1 * 4 + 0][r1] = ra1.x; As[s][kq1 * 4 + 1][r1] = ra1.y;        \
        As[s][kq1 * 4 + 2][r1] = ra1.z; As[s][kq1 * 4 + 3][r1] = ra1.w;        \
        *(float4*)&Bs[s][bk0][bc0 * 4] = rb0;                                  \
        *(float4*)&Bs[s][bk1][bc0 * 4] = rb1; }
    STORE_SLICE_P(0);
    __syncthreads();
    unsigned bs0 = smem_u32(&Bs[0][0][0]) + tx * 32;
#pragma unroll 1
    for (int i = 0; i < 16; i++) {
        if (i < 15) {
            int k0 = (i + 1) * 16;
            ra0 = *(const float4*)(Wr0 + k0); ra1 = *(const float4*)(Wr1 + k0);
            rb0 = *(const float4*)(Bg0 + (size_t)k0 * NW);
            rb1 = *(const float4*)(Bg1 + (size_t)k0 * NW);
        }
        const float(*Asl)[132] = As[i & 1];
        unsigned bsb = bs0 + (i & 1) * (16 * 132 * 4);
#pragma unroll
        for (int k = 0; k < 16; k++) {
            float4 a0 = *(const float4*)&Asl[k][ty * 8];
            float4 a1 = *(const float4*)&Asl[k][ty * 8 + 4];
            u64 b0, b1, b2, b3;
            lds128_u64(b0, b1, bsb + k * 528);
            lds128_u64(b2, b3, bsb + k * 528 + 16);
            float am[8] = {a0.x, a0.y, a0.z, a0.w, a1.x, a1.y, a1.z, a1.w};
#pragma unroll
            for (int m = 0; m < 8; m++) {
                u64 ad = f2_dup(am[m]);
                fma2(acc[m][0], ad, b0); fma2(acc[m][1], ad, b1);
                fma2(acc[m][2], ad, b2); fma2(acc[m][3], ad, b3);
            }
        }
        __syncthreads();
        if (i < 15) {
            STORE_SLICE_P((i + 1) & 1);
            __syncthreads();
        }
    }
    float f[8][8];
#pragma unroll
    for (int m = 0; m < 8; m++)
#pragma unroll
        for (int n = 0; n < 4; n++) f2_unpack(f[m][2 * n], f[m][2 * n + 1], acc[m][n]);
    float bb[8];
#pragma unroll
    for (int m = 0; m < 8; m++) bb[m] = bias[o0 + ty * 8 + m];
#pragma unroll
    for (int nn = 0; nn < 8; nn++) {
        float* dst = &g_proj[((size_t)b * NW + n0 + tx * 8 + nn) * Cv + o0 + ty * 8];
        *(float4*)dst = make_float4(f[0][nn] + bb[0], f[1][nn] + bb[1],
                                    f[2][nn] + bb[2], f[3][nn] + bb[3]);
        *(float4*)(dst + 4) = make_float4(f[4][nn] + bb[4], f[5][nn] + bb[5],
                                          f[6][nn] + bb[6], f[7][nn] + bb[7]);
    }
#undef STORE_SLICE_P
}

// ---------------- kernel 7: scatter back to pixels, planar output -----------
__global__ void scatter_kernel(float* __restrict__ out) {
    __shared__ float aff_s[32 * 144];
    __shared__ float r_s[3 * 34 * 33];
    int Y = blockIdx.x, b = blockIdx.y;
    int tid = threadIdx.x;
    int X = tid >> 2, px = tid & 3;
    const float* ab = g_aff + ((size_t)b * NW + Y * 32) * 144;
    for (int idx = tid; idx < 4608; idx += 128) aff_s[idx] = ab[idx];
    for (int idx = tid; idx < 3 * 34 * 33; idx += 128) r_s[idx] = 0.f;
    __syncthreads();
    float a[4][9];
#pragma unroll
    for (int py = 0; py < 4; py++)
#pragma unroll
        for (int i = 0; i < 9; i++)
            a[py][i] = aff_s[X * 144 + (py * 4 + px) * 9 + i];

    for (int c0 = 0; c0 < 256; c0 += 32) {
        __syncthreads();
        for (int idx = tid; idx < 3 * 32 * 32; idx += 128) {
            int dy = idx >> 10;
            int rem = idx & 1023;
            int Xl = rem >> 5, cc = rem & 31;
            int ny = Y + dy - 1;
            if ((unsigned)ny < 32u)
                r_s[((dy * 34) + Xl + 1) * 33 + cc] =
                    g_proj[((size_t)b * NW + ny * 32 + Xl) * Cv + c0 + cc];
        }
        __syncthreads();
#pragma unroll
        for (int py = 0; py < 4; py++) {
            size_t obase = ((size_t)b * 256 + c0) * 16384 +
                           (size_t)(Y * 4 + py) * 128 + tid;
#pragma unroll 4
            for (int c = 0; c < 32; c++) {
                float v = 0.f;
#pragma unroll
                for (int i = 0; i < 9; i++) {
                    int dy = i / 3, dx = i % 3;
                    v = fmaf(r_s[((dy * 34) + X + dx) * 33 + c], a[py][i], v);
                }
                out[obase + (size_t)c * 16384] = v;
            }
        }
    }
}

// ---------------- launch ----------------
extern "C" void kernel_launch(void* const* d_in, const int* in_sizes, int n_in,
                              void* d_out, int out_size) {
    const float* x = nullptr; const float* qkv_w = nullptr;
    const float* proj_w = nullptr; const float* proj_b = nullptr;
    for (int i = 0; i < n_in; i++) {
        int s = in_sizes[i];
        if (s == 8 * 16384 * 256) x = (const float*)d_in[i];
        else if (s == 768 * 256)  qkv_w = (const float*)d_in[i];
        else if (s == 256 * 256)  proj_w = (const float*)d_in[i];
        else if (s == 256)        proj_b = (const float*)d_in[i];
    }
    float* out = (float*)d_out;

    pool_kernel<<<dim3(256, 8), 256>>>(x);
    aff_kernel<<<dim3(1024, 8), 256>>>(x);
    fold_kernel<<<dim3(256, 8), 256>>>();
    gemm_qkv<<<dim3(8, 6, 8), 256>>>(qkv_w);
    attn_kernel<<<dim3(4, 8, 8), 256>>>();
    gemm_proj<<<dim3(8, 2, 8), 256>>>(proj_w, proj_b);
    scatter_kernel<<<dim3(32, 8), 128>>>(out);
}

// round 7
// speedup vs baseline: 1.2566x; 1.0931x over previous
#include <cuda_runtime.h>
#include <cuda_bf16.h>
#include <math.h>
#include <stdint.h>

#define Bv 8
#define Cv 256
#define NW 1024      // 32*32 super tokens
#define NHEADS 8
#define HD 32

// ---------------- scratch (static device memory; no allocs) ----------------
__device__ float g_wf[Bv * NW * Cv];                 // (b, t, c)
__device__ float g_aff[Bv * NW * 16 * 9];            // (b, t, p, i)
__device__ float g_wf2raw[(size_t)Bv * NW * 9 * Cv]; // (b, t, i, c)
__device__ float g_affsumraw[Bv * NW * 9];           // (b, t, i)
__device__ __nv_bfloat16 g_wf2h[Bv * NW * Cv];       // tokens hi (b, t, c)
__device__ __nv_bfloat16 g_wf2l[Bv * NW * Cv];       // tokens lo
__device__ __nv_bfloat16 g_qkvwh[768 * 256];         // qkv weight hi (o,k)
__device__ __nv_bfloat16 g_qkvwl[768 * 256];
__device__ __nv_bfloat16 g_pwh[256 * 256];           // proj weight hi (o,k)
__device__ __nv_bfloat16 g_pwl[256 * 256];
__device__ float g_qkvT[(size_t)Bv * NW * 768];      // (b, n, o) token-major qkv
__device__ __nv_bfloat16 g_aoh[Bv * NW * Cv];        // attn out hi (b, n, c)
__device__ __nv_bfloat16 g_aol[Bv * NW * Cv];        // attn out lo
__device__ float g_proj[(size_t)Bv * NW * Cv];       // (b, n, o)

// ---------------- f32x2 packed-math helpers (sm_103a) ----------------
typedef unsigned long long u64;
__device__ __forceinline__ u64 f2_dup(float a) {
    u64 d; asm("mov.b64 %0, {%1, %1};" : "=l"(d) : "f"(a)); return d;
}
__device__ __forceinline__ u64 f2_pack(float a, float b) {
    u64 d; asm("mov.b64 %0, {%1, %2};" : "=l"(d) : "f"(a), "f"(b)); return d;
}
__device__ __forceinline__ void f2_unpack(float& a, float& b, u64 d) {
    asm("mov.b64 {%0, %1}, %2;" : "=f"(a), "=f"(b) : "l"(d));
}
__device__ __forceinline__ void fma2(u64& c, u64 a, u64 b) {
    asm("fma.rn.f32x2 %0, %1, %2, %0;" : "+l"(c) : "l"(a), "l"(b));
}
__device__ __forceinline__ u64 add2(u64 a, u64 b) {
    u64 d; asm("add.rn.f32x2 %0, %1, %2;" : "=l"(d) : "l"(a), "l"(b)); return d;
}
__device__ __forceinline__ void lds128_u64(u64& lo, u64& hi, unsigned saddr) {
    asm volatile("ld.shared.v2.u64 {%0, %1}, [%2];" : "=l"(lo), "=l"(hi) : "r"(saddr));
}
__device__ __forceinline__ unsigned lds32(unsigned saddr) {
    unsigned v;
    asm volatile("ld.shared.b32 %0, [%1];" : "=r"(v) : "r"(saddr));
    return v;
}
__device__ __forceinline__ unsigned smem_u32(const void* p) {
    unsigned a;
    asm("{ .reg .u64 t; cvta.to.shared.u64 t, %1; cvt.u32.u64 %0, t; }" : "=r"(a) : "l"(p));
    return a;
}

// ---------------- mma.sync + cp.async helpers (portable sm_80+) -------------
__device__ __forceinline__ void mma16816(float* c, const unsigned* a, const unsigned* b) {
    asm volatile(
        "mma.sync.aligned.m16n8k16.row.col.f32.bf16.bf16.f32 "
        "{%0,%1,%2,%3}, {%4,%5,%6,%7}, {%8,%9}, {%0,%1,%2,%3};"
        : "+f"(c[0]), "+f"(c[1]), "+f"(c[2]), "+f"(c[3])
        : "r"(a[0]), "r"(a[1]), "r"(a[2]), "r"(a[3]), "r"(b[0]), "r"(b[1]));
}
#define CPA16(dst, src) \
    asm volatile("cp.async.ca.shared.global [%0], [%1], 16;" :: "r"(dst), "l"(src))
#define CPA_COMMIT() asm volatile("cp.async.commit_group;" ::: "memory")
#define CPA_WAIT(n)  asm volatile("cp.async.wait_group %0;" :: "n"(n) : "memory")

// ---------------- kernel 1: 4x4 average pool -> wf (float4) ----------------
__global__ void pool_kernel(const float* __restrict__ x) {
    int b = blockIdx.y;
    int t = blockIdx.x * 4 + (threadIdx.x >> 6);
    int c4 = (threadIdx.x & 63) * 4;
    int Y = t >> 5, X = t & 31;
    const float* xb = x + (size_t)b * 16384 * 256;
    float4 s = make_float4(0.f, 0.f, 0.f, 0.f);
#pragma unroll
    for (int py = 0; py < 4; py++)
#pragma unroll
        for (int px = 0; px < 4; px++) {
            int n = (Y * 4 + py) * 128 + X * 4 + px;
            float4 v = *(const float4*)&xb[(size_t)n * 256 + c4];
            s.x += v.x; s.y += v.y; s.z += v.z; s.w += v.w;
        }
    s.x *= (1.f / 16.f); s.y *= (1.f / 16.f); s.z *= (1.f / 16.f); s.w *= (1.f / 16.f);
    *(float4*)&g_wf[((size_t)b * NW + t) * Cv + c4] = s;
}

// ---------------- weight conversion: fp32 -> bf16 hi/lo ----------------
__global__ void conv_w(const float* __restrict__ src, int which, int nElt) {
    int i = blockIdx.x * 256 + threadIdx.x;
    if (i >= nElt) return;
    float x = src[i];
    __nv_bfloat16 h = __float2bfloat16(x);
    __nv_bfloat16 l = __float2bfloat16(x - __bfloat162float(h));
    if (which == 0) { g_qkvwh[i] = h; g_qkvwl[i] = l; }
    else            { g_pwh[i] = h;  g_pwl[i] = l; }
}

// ---------------- kernel 2: affinity softmax + wf2 window partials ----------
__global__ void aff_kernel(const float* __restrict__ x) {
    __shared__ float pix[16][256];
    __shared__ float wfu[9][256];
    __shared__ float lg[16][9];
    __shared__ float affs[16][9];
    int b = blockIdx.y, t = blockIdx.x, tid = threadIdx.x;
    int Y = t >> 5, X = t & 31;
    const float* xb = x + (size_t)b * 16384 * 256;
    {
        int c4 = (tid & 63) * 4;
#pragma unroll
        for (int pp = 0; pp < 4; pp++) {
            int p = pp * 4 + (tid >> 6);
            int n = (Y * 4 + (p >> 2)) * 128 + X * 4 + (p & 3);
            *(float4*)&pix[p][c4] = *(const float4*)&xb[(size_t)n * 256 + c4];
        }
#pragma unroll
        for (int ii = 0; ii < 3; ii++) {
            int i = ii * 4 + (tid >> 6);
            if (i < 9) {
                int ny = Y + (i / 3) - 1, nx = X + (i % 3) - 1;
                float4 v = make_float4(0.f, 0.f, 0.f, 0.f);
                if ((unsigned)ny < 32u && (unsigned)nx < 32u)
                    v = *(const float4*)&g_wf[((size_t)b * NW + ny * 32 + nx) * Cv + c4];
                *(float4*)&wfu[i][c4] = v;
            }
        }
    }
    __syncthreads();
    int warp = tid >> 5, lane = tid & 31;
    for (int pair = warp; pair < 144; pair += 8) {
        int p = pair / 9, i = pair % 9;
        float s = 0.f;
#pragma unroll
        for (int k = 0; k < 8; k++) s += pix[p][lane + 32 * k] * wfu[i][lane + 32 * k];
#pragma unroll
        for (int off = 16; off; off >>= 1) s += __shfl_down_sync(0xffffffffu, s, off);
        if (lane == 0) lg[p][i] = s * 0.0625f;
    }
    __syncthreads();
    if (tid < 16) {
        float m = -1e30f;
#pragma unroll
        for (int i = 0; i < 9; i++) m = fmaxf(m, lg[tid][i]);
        float e[9], sum = 0.f;
#pragma unroll
        for (int i = 0; i < 9; i++) { e[i] = __expf(lg[tid][i] - m); sum += e[i]; }
        float inv = 1.f / sum;
#pragma unroll
        for (int i = 0; i < 9; i++) affs[tid][i] = e[i] * inv;
    }
    __syncthreads();
    if (tid < 144)
        g_aff[((size_t)b * NW + t) * 144 + tid] = affs[tid / 9][tid % 9];
    if (tid >= 160 && tid < 169) {
        int i = tid - 160;
        float s = 0.f;
#pragma unroll
        for (int p = 0; p < 16; p++) s += affs[p][i];
        g_affsumraw[((size_t)b * NW + t) * 9 + i] = s;
    }
    float acc[9];
#pragma unroll
    for (int i = 0; i < 9; i++) acc[i] = 0.f;
#pragma unroll
    for (int p = 0; p < 16; p++) {
        float v = pix[p][tid];
#pragma unroll
        for (int i = 0; i < 9; i++) acc[i] = fmaf(v, affs[p][i], acc[i]);
    }
    size_t base = ((size_t)b * NW + t) * 9 * Cv;
#pragma unroll
    for (int i = 0; i < 9; i++) g_wf2raw[base + (size_t)i * Cv + tid] = acc[i];
}

// ---------------- kernel 3: fold-gather + normalize -> bf16 hi/lo -----------
__global__ void fold_kernel() {
    int b = blockIdx.y;
    int t = blockIdx.x * 4 + (threadIdx.x >> 6);
    int c = (threadIdx.x & 63) * 4;
    int Y = t >> 5, X = t & 31;
    float4 acc = make_float4(0.f, 0.f, 0.f, 0.f);
    float asum = 0.f;
#pragma unroll
    for (int i = 0; i < 9; i++) {
        int ny = Y - ((i / 3) - 1), nx = X - ((i % 3) - 1);
        if ((unsigned)ny < 32u && (unsigned)nx < 32u) {
            size_t nb = (size_t)b * NW + ny * 32 + nx;
            float4 v = *(const float4*)&g_wf2raw[(nb * 9 + i) * Cv + c];
            acc.x += v.x; acc.y += v.y; acc.z += v.z; acc.w += v.w;
            asum += g_affsumraw[nb * 9 + i];
        }
    }
    float inv = 1.f / (asum + 1e-12f);
    float f[4] = {acc.x * inv, acc.y * inv, acc.z * inv, acc.w * inv};
    size_t off = ((size_t)b * NW + t) * Cv + c;
    __nv_bfloat162 h01, h23, l01, l23;
    h01.x = __float2bfloat16(f[0]); h01.y = __float2bfloat16(f[1]);
    h23.x = __float2bfloat16(f[2]); h23.y = __float2bfloat16(f[3]);
    l01.x = __float2bfloat16(f[0] - __bfloat162float(h01.x));
    l01.y = __float2bfloat16(f[1] - __bfloat162float(h01.y));
    l23.x = __float2bfloat16(f[2] - __bfloat162float(h23.x));
    l23.y = __float2bfloat16(f[3] - __bfloat162float(h23.y));
    *(__nv_bfloat162*)&g_wf2h[off] = h01;
    *(__nv_bfloat162*)&g_wf2h[off + 2] = h23;
    *(__nv_bfloat162*)&g_wf2l[off] = l01;
    *(__nv_bfloat162*)&g_wf2l[off + 2] = l23;
}

// ---------------- GEMM via mma.sync bf16 (3-term hi/lo split) ---------------
// out[b][n][o] = sum_k A[b][n][k] * B[o][k]; A = tokens hi/lo, B = weights hi/lo.
// Block tile M=128 (tokens) x N=128 (outputs), K chunks of 32, cp.async 2-stage.
// smem stage layout: Ah @0, Al @10240, Bh @20480, Bl @30720; stage stride 40960.
// Row stride 80B (40 bf16, 64B data + 16B pad) -> conflict-free frag LDS.
#define STG_STRIDE 40960
__global__ void __launch_bounds__(256) gemm_mma(int which,
                                                const float* __restrict__ bias,
                                                int outStride) {
    extern __shared__ __align__(16) char sm[];
    int b = blockIdx.z;
    int n0 = blockIdx.x * 128, o0 = blockIdx.y * 128;
    int tid = threadIdx.x;
    int w = tid >> 5, lane = tid & 31, g = lane >> 2, t = lane & 3;
    int wm = (w >> 2) * 64, wn = (w & 3) * 32;

    const __nv_bfloat16* Ah = (which == 0 ? g_wf2h : g_aoh) + (size_t)b * NW * Cv;
    const __nv_bfloat16* Al = (which == 0 ? g_wf2l : g_aol) + (size_t)b * NW * Cv;
    const __nv_bfloat16* Bh = (which == 0 ? g_qkvwh : g_pwh);
    const __nv_bfloat16* Bl = (which == 0 ? g_qkvwl : g_pwl);
    float* out = (which == 0 ? g_qkvT : g_proj);

    unsigned smb = smem_u32(sm);
    // loader: two rows per thread per array
    int lr0 = tid >> 2, lq = tid & 3;
    int lr1 = lr0 + 64;
    unsigned sd0 = lr0 * 80 + lq * 16;
    unsigned sd1 = lr1 * 80 + lq * 16;

    float acc[4][4][4];
#pragma unroll
    for (int mt = 0; mt < 4; mt++)
#pragma unroll
        for (int nt = 0; nt < 4; nt++)
#pragma unroll
            for (int j = 0; j < 4; j++) acc[mt][nt][j] = 0.f;

#define ISSUE_CHUNK(kc, s) do {                                                \
    unsigned sb = smb + (s) * STG_STRIDE;                                      \
    size_t ga0 = (size_t)(n0 + lr0) * 256 + (kc) * 32 + lq * 8;                \
    size_t ga1 = (size_t)(n0 + lr1) * 256 + (kc) * 32 + lq * 8;                \
    size_t gb0 = (size_t)(o0 + lr0) * 256 + (kc) * 32 + lq * 8;                \
    size_t gb1 = (size_t)(o0 + lr1) * 256 + (kc) * 32 + lq * 8;                \
    CPA16(sb + sd0,         Ah + ga0);  CPA16(sb + sd1,         Ah + ga1);     \
    CPA16(sb + 10240 + sd0, Al + ga0);  CPA16(sb + 10240 + sd1, Al + ga1);     \
    CPA16(sb + 20480 + sd0, Bh + gb0);  CPA16(sb + 20480 + sd1, Bh + gb1);     \
    CPA16(sb + 30720 + sd0, Bl + gb0);  CPA16(sb + 30720 + sd1, Bl + gb1);     \
    CPA_COMMIT();                                                              \
} while (0)

    ISSUE_CHUNK(0, 0);
    ISSUE_CHUNK(1, 1);
#pragma unroll 1
    for (int c = 0; c < 8; c++) {
        if (c < 7) { CPA_WAIT(1); } else { CPA_WAIT(0); }
        __syncthreads();
        unsigned stage = smb + (c & 1) * STG_STRIDE;
#pragma unroll
        for (int ks = 0; ks < 2; ks++) {
            unsigned kb = ks * 32;
            unsigned bhf[4][2], blf[4][2];
#pragma unroll
            for (int nt = 0; nt < 4; nt++) {
                unsigned ba = stage + 20480 + (unsigned)(wn + nt * 8 + g) * 80 + t * 4 + kb;
                bhf[nt][0] = lds32(ba);          bhf[nt][1] = lds32(ba + 16);
                blf[nt][0] = lds32(ba + 10240);  blf[nt][1] = lds32(ba + 10256);
            }
#pragma unroll
            for (int mt = 0; mt < 4; mt++) {
                unsigned aa = stage + (unsigned)(wm + mt * 16 + g) * 80 + t * 4 + kb;
                unsigned ahf[4], alf[4];
                ahf[0] = lds32(aa);        ahf[1] = lds32(aa + 640);
                ahf[2] = lds32(aa + 16);   ahf[3] = lds32(aa + 656);
                alf[0] = lds32(aa + 10240);        alf[1] = lds32(aa + 10880);
                alf[2] = lds32(aa + 10256);        alf[3] = lds32(aa + 10896);
#pragma unroll
                for (int nt = 0; nt < 4; nt++) {
                    mma16816(acc[mt][nt], ahf, bhf[nt]);
                    mma16816(acc[mt][nt], ahf, blf[nt]);
                    mma16816(acc[mt][nt], alf, bhf[nt]);
                }
            }
        }
        __syncthreads();
        if (c < 6) ISSUE_CHUNK(c + 2, c & 1);
    }
#undef ISSUE_CHUNK

#pragma unroll
    for (int nt = 0; nt < 4; nt++) {
        int col = o0 + wn + nt * 8 + t * 2;
        float b0 = 0.f, b1 = 0.f;
        if (bias) { b0 = __ldg(&bias[col]); b1 = __ldg(&bias[col + 1]); }
#pragma unroll
        for (int mt = 0; mt < 4; mt++) {
            int row = n0 + wm + mt * 16 + g;
            float* p = out + ((size_t)b * NW + row) * outStride + col;
            *(float2*)p = make_float2(acc[mt][nt][0] + b0, acc[mt][nt][1] + b1);
            *(float2*)(p + (size_t)8 * outStride) =
                make_float2(acc[mt][nt][2] + b0, acc[mt][nt][3] + b1);
        }
    }
}

// ---------------- kernel 5: attention (token-major qkv), f32x2 --------------
__global__ void __launch_bounds__(256, 2) attn_kernel() {
    __shared__ __align__(16) float ks[128][36];
    __shared__ __align__(16) float vs[128][36];
    int b = blockIdx.z, h = blockIdx.y;
    int tid = threadIdx.x;
    int m = blockIdx.x * 256 + tid;
    const float hs = 0.17677669529663687f;
    const float* qrow = g_qkvT + ((size_t)b * NW + m) * 768 + h * 96;
    u64 q2[16], a2[16];
#pragma unroll
    for (int i = 0; i < 8; i++) {
        float4 qv = ((const float4*)qrow)[i];
        q2[2 * i] = f2_pack(qv.x * hs, qv.y * hs);
        q2[2 * i + 1] = f2_pack(qv.z * hs, qv.w * hs);
    }
#pragma unroll
    for (int i = 0; i < 16; i++) a2[i] = 0ull;
    float l = 0.f;
    unsigned ks_base = smem_u32(&ks[0][0]);
    unsigned vs_base = smem_u32(&vs[0][0]);
    for (int n0 = 0; n0 < 1024; n0 += 128) {
        __syncthreads();
#pragma unroll
        for (int r = 0; r < 4; r++) {
            int idx = r * 256 + tid;
            int n = idx >> 3, j = idx & 7;
            const float4* row = (const float4*)(g_qkvT + ((size_t)b * NW + n0 + n) * 768 + h * 96);
            *(float4*)&ks[n][j * 4] = row[8 + j];   // K at +32 floats
            *(float4*)&vs[n][j * 4] = row[16 + j];  // V at +64 floats
        }
        __syncthreads();
#pragma unroll 2
        for (int n = 0; n < 128; n += 2) {
            unsigned ka = ks_base + n * 144;
            u64 sA0 = 0ull, sA1 = 0ull, sB0 = 0ull, sB1 = 0ull;
            u64 klo, khi;
            lds128_u64(klo, khi, ka);       fma2(sA0, q2[0], klo);  fma2(sA1, q2[1], khi);
            lds128_u64(klo, khi, ka + 16);  fma2(sA0, q2[2], klo);  fma2(sA1, q2[3], khi);
            lds128_u64(klo, khi, ka + 32);  fma2(sA0, q2[4], klo);  fma2(sA1, q2[5], khi);
            lds128_u64(klo, khi, ka + 48);  fma2(sA0, q2[6], klo);  fma2(sA1, q2[7], khi);
            lds128_u64(klo, khi, ka + 64);  fma2(sA0, q2[8], klo);  fma2(sA1, q2[9], khi);
            lds128_u64(klo, khi, ka + 80);  fma2(sA0, q2[10], klo); fma2(sA1, q2[11], khi);
            lds128_u64(klo, khi, ka + 96);  fma2(sA0, q2[12], klo); fma2(sA1, q2[13], khi);
            lds128_u64(klo, khi, ka + 112); fma2(sA0, q2[14], klo); fma2(sA1, q2[15], khi);
            lds128_u64(klo, khi, ka + 144);       fma2(sB0, q2[0], klo);  fma2(sB1, q2[1], khi);
            lds128_u64(klo, khi, ka + 144 + 16);  fma2(sB0, q2[2], klo);  fma2(sB1, q2[3], khi);
            lds128_u64(klo, khi, ka + 144 + 32);  fma2(sB0, q2[4], klo);  fma2(sB1, q2[5], khi);
            lds128_u64(klo, khi, ka + 144 + 48);  fma2(sB0, q2[6], klo);  fma2(sB1, q2[7], khi);
            lds128_u64(klo, khi, ka + 144 + 64);  fma2(sB0, q2[8], klo);  fma2(sB1, q2[9], khi);
            lds128_u64(klo, khi, ka + 144 + 80);  fma2(sB0, q2[10], klo); fma2(sB1, q2[11], khi);
            lds128_u64(klo, khi, ka + 144 + 96);  fma2(sB0, q2[12], klo); fma2(sB1, q2[13], khi);
            lds128_u64(klo, khi, ka + 144 + 112); fma2(sB0, q2[14], klo); fma2(sB1, q2[15], khi);
            u64 stA = add2(sA0, sA1);
            u64 stB = add2(sB0, sB1);
            float ax, ay, bx, by;
            f2_unpack(ax, ay, stA);
            f2_unpack(bx, by, stB);
            float pA = __expf(ax + ay);
            float pB = __expf(bx + by);
            l += pA + pB;
            u64 pA2 = f2_dup(pA), pB2 = f2_dup(pB);
            unsigned va = vs_base + n * 144;
            u64 v0, v1;
#pragma unroll
            for (int i = 0; i < 8; i++) {
                lds128_u64(v0, v1, va + 16 * i);
                fma2(a2[2 * i], pA2, v0);
                fma2(a2[2 * i + 1], pA2, v1);
            }
#pragma unroll
            for (int i = 0; i < 8; i++) {
                lds128_u64(v0, v1, va + 144 + 16 * i);
                fma2(a2[2 * i], pB2, v0);
                fma2(a2[2 * i + 1], pB2, v1);
            }
        }
    }
    float inv = 1.f / l;
    size_t obase = ((size_t)b * NW + m) * Cv + h * 32;
#pragma unroll
    for (int i = 0; i < 16; i++) {
        float x, y;
        f2_unpack(x, y, a2[i]);
        x *= inv; y *= inv;
        __nv_bfloat162 hv, lv;
        hv.x = __float2bfloat16(x); hv.y = __float2bfloat16(y);
        lv.x = __float2bfloat16(x - __bfloat162float(hv.x));
        lv.y = __float2bfloat16(y - __bfloat162float(hv.y));
        *(__nv_bfloat162*)&g_aoh[obase + 2 * i] = hv;
        *(__nv_bfloat162*)&g_aol[obase + 2 * i] = lv;
    }
}

// ---------------- kernel 7: scatter back to pixels, planar output -----------
__global__ void scatter_kernel(float* __restrict__ out) {
    __shared__ float aff_s[32 * 144];
    __shared__ float r_s[3 * 34 * 33];
    int Y = blockIdx.x, b = blockIdx.y;
    int tid = threadIdx.x;
    int X = tid >> 2, px = tid & 3;
    const float* ab = g_aff + ((size_t)b * NW + Y * 32) * 144;
    for (int idx = tid; idx < 4608; idx += 128) aff_s[idx] = ab[idx];
    for (int idx = tid; idx < 3 * 34 * 33; idx += 128) r_s[idx] = 0.f;
    __syncthreads();
    float a[4][9];
#pragma unroll
    for (int py = 0; py < 4; py++)
#pragma unroll
        for (int i = 0; i < 9; i++)
            a[py][i] = aff_s[X * 144 + (py * 4 + px) * 9 + i];

    for (int c0 = 0; c0 < 256; c0 += 32) {
        __syncthreads();
        for (int idx = tid; idx < 3 * 32 * 32; idx += 128) {
            int dy = idx >> 10;
            int rem = idx & 1023;
            int Xl = rem >> 5, cc = rem & 31;
            int ny = Y + dy - 1;
            if ((unsigned)ny < 32u)
                r_s[((dy * 34) + Xl + 1) * 33 + cc] =
                    g_proj[((size_t)b * NW + ny * 32 + Xl) * Cv + c0 + cc];
        }
        __syncthreads();
#pragma unroll
        for (int py = 0; py < 4; py++) {
            size_t obase = ((size_t)b * 256 + c0) * 16384 +
                           (size_t)(Y * 4 + py) * 128 + tid;
#pragma unroll 4
            for (int c = 0; c < 32; c++) {
                float v = 0.f;
#pragma unroll
                for (int i = 0; i < 9; i++) {
                    int dy = i / 3, dx = i % 3;
                    v = fmaf(r_s[((dy * 34) + X + dx) * 33 + c], a[py][i], v);
                }
                out[obase + (size_t)c * 16384] = v;
            }
        }
    }
}

// ---------------- launch ----------------
extern "C" void kernel_launch(void* const* d_in, const int* in_sizes, int n_in,
                              void* d_out, int out_size) {
    const float* x = nullptr; const float* qkv_w = nullptr;
    const float* proj_w = nullptr; const float* proj_b = nullptr;
    for (int i = 0; i < n_in; i++) {
        int s = in_sizes[i];
        if (s == 8 * 16384 * 256) x = (const float*)d_in[i];
        else if (s == 768 * 256)  qkv_w = (const float*)d_in[i];
        else if (s == 256 * 256)  proj_w = (const float*)d_in[i];
        else if (s == 256)        proj_b = (const float*)d_in[i];
    }
    float* out = (float*)d_out;

    const int DSMEM = 2 * STG_STRIDE;   // 80 KB: 2 stages x (Ah,Al,Bh,Bl)
    cudaFuncSetAttribute(gemm_mma, cudaFuncAttributeMaxDynamicSharedMemorySize, DSMEM);

    pool_kernel<<<dim3(256, 8), 256>>>(x);
    conv_w<<<768, 256>>>(qkv_w, 0, 768 * 256);
    conv_w<<<256, 256>>>(proj_w, 1, 256 * 256);
    aff_kernel<<<dim3(1024, 8), 256>>>(x);
    fold_kernel<<<dim3(256, 8), 256>>>();
    gemm_mma<<<dim3(8, 6, 8), 256, DSMEM>>>(0, nullptr, 768);
    attn_kernel<<<dim3(4, 8, 8), 256>>>();
    gemm_mma<<<dim3(8, 2, 8), 256, DSMEM>>>(1, proj_b, 256);
    scatter_kernel<<<dim3(32, 8), 128>>>(out);
}

// round 8
// speedup vs baseline: 1.3531x; 1.0769x over previous
#include <cuda_runtime.h>
#include <cuda_bf16.h>
#include <math.h>
#include <stdint.h>

#define Bv 8
#define Cv 256
#define NW 1024      // 32*32 super tokens
#define NHEADS 8
#define HD 32

// ---------------- scratch (static device memory; no allocs) ----------------
__device__ float g_wf[Bv * NW * Cv];                 // (b, t, c)
__device__ float g_aff[Bv * NW * 16 * 9];            // (b, t, p, i)
__device__ float g_wf2raw[(size_t)Bv * NW * 9 * Cv]; // (b, t, i, c)
__device__ float g_affsumraw[Bv * NW * 9];           // (b, t, i)
__device__ __nv_bfloat16 g_wf2h[Bv * NW * Cv];       // tokens hi (b, t, c)
__device__ __nv_bfloat16 g_wf2l[Bv * NW * Cv];       // tokens lo
__device__ __nv_bfloat16 g_qkvwh[768 * 256];         // qkv weight hi (o,k)
__device__ __nv_bfloat16 g_qkvwl[768 * 256];
__device__ __nv_bfloat16 g_pwh[256 * 256];           // proj weight hi (o,k)
__device__ __nv_bfloat16 g_pwl[256 * 256];
__device__ float g_qkvT[(size_t)Bv * NW * 768];      // (b, n, o) token-major qkv
__device__ __nv_bfloat16 g_aoh[Bv * NW * Cv];        // attn out hi (b, n, c)
__device__ __nv_bfloat16 g_aol[Bv * NW * Cv];        // attn out lo
__device__ float g_proj[(size_t)Bv * NW * Cv];       // (b, n, o)

// ---------------- f32x2 packed-math helpers (sm_103a) ----------------
typedef unsigned long long u64;
__device__ __forceinline__ u64 f2_dup(float a) {
    u64 d; asm("mov.b64 %0, {%1, %1};" : "=l"(d) : "f"(a)); return d;
}
__device__ __forceinline__ u64 f2_pack(float a, float b) {
    u64 d; asm("mov.b64 %0, {%1, %2};" : "=l"(d) : "f"(a), "f"(b)); return d;
}
__device__ __forceinline__ void f2_unpack(float& a, float& b, u64 d) {
    asm("mov.b64 {%0, %1}, %2;" : "=f"(a), "=f"(b) : "l"(d));
}
__device__ __forceinline__ void fma2(u64& c, u64 a, u64 b) {
    asm("fma.rn.f32x2 %0, %1, %2, %0;" : "+l"(c) : "l"(a), "l"(b));
}
__device__ __forceinline__ u64 add2(u64 a, u64 b) {
    u64 d; asm("add.rn.f32x2 %0, %1, %2;" : "=l"(d) : "l"(a), "l"(b)); return d;
}
__device__ __forceinline__ void lds128_u64(u64& lo, u64& hi, unsigned saddr) {
    asm volatile("ld.shared.v2.u64 {%0, %1}, [%2];" : "=l"(lo), "=l"(hi) : "r"(saddr));
}
__device__ __forceinline__ u64 lds64(unsigned saddr) {
    u64 v;
    asm volatile("ld.shared.b64 %0, [%1];" : "=l"(v) : "r"(saddr));
    return v;
}
__device__ __forceinline__ unsigned lds32(unsigned saddr) {
    unsigned v;
    asm volatile("ld.shared.b32 %0, [%1];" : "=r"(v) : "r"(saddr));
    return v;
}
__device__ __forceinline__ unsigned smem_u32(const void* p) {
    unsigned a;
    asm("{ .reg .u64 t; cvta.to.shared.u64 t, %1; cvt.u32.u64 %0, t; }" : "=r"(a) : "l"(p));
    return a;
}

// ---------------- mma.sync + cp.async helpers (portable sm_80+) -------------
__device__ __forceinline__ void mma16816(float* c, const unsigned* a, const unsigned* b) {
    asm volatile(
        "mma.sync.aligned.m16n8k16.row.col.f32.bf16.bf16.f32 "
        "{%0,%1,%2,%3}, {%4,%5,%6,%7}, {%8,%9}, {%0,%1,%2,%3};"
        : "+f"(c[0]), "+f"(c[1]), "+f"(c[2]), "+f"(c[3])
        : "r"(a[0]), "r"(a[1]), "r"(a[2]), "r"(a[3]), "r"(b[0]), "r"(b[1]));
}
#define CPA16(dst, src) \
    asm volatile("cp.async.ca.shared.global [%0], [%1], 16;" :: "r"(dst), "l"(src))
#define CPA_COMMIT() asm volatile("cp.async.commit_group;" ::: "memory")
#define CPA_WAIT(n)  asm volatile("cp.async.wait_group %0;" :: "n"(n) : "memory")

// ---------------- kernel 1: 4x4 average pool -> wf (float4) ----------------
__global__ void pool_kernel(const float* __restrict__ x) {
    int b = blockIdx.y;
    int t = blockIdx.x * 4 + (threadIdx.x >> 6);
    int c4 = (threadIdx.x & 63) * 4;
    int Y = t >> 5, X = t & 31;
    const float* xb = x + (size_t)b * 16384 * 256;
    float4 s = make_float4(0.f, 0.f, 0.f, 0.f);
#pragma unroll
    for (int py = 0; py < 4; py++)
#pragma unroll
        for (int px = 0; px < 4; px++) {
            int n = (Y * 4 + py) * 128 + X * 4 + px;
            float4 v = *(const float4*)&xb[(size_t)n * 256 + c4];
            s.x += v.x; s.y += v.y; s.z += v.z; s.w += v.w;
        }
    s.x *= (1.f / 16.f); s.y *= (1.f / 16.f); s.z *= (1.f / 16.f); s.w *= (1.f / 16.f);
    *(float4*)&g_wf[((size_t)b * NW + t) * Cv + c4] = s;
}

// ---------------- weight conversion: fp32 -> bf16 hi/lo ----------------
__global__ void conv_w(const float* __restrict__ src, int which, int nElt) {
    int i = blockIdx.x * 256 + threadIdx.x;
    if (i >= nElt) return;
    float x = src[i];
    __nv_bfloat16 h = __float2bfloat16(x);
    __nv_bfloat16 l = __float2bfloat16(x - __bfloat162float(h));
    if (which == 0) { g_qkvwh[i] = h; g_qkvwl[i] = l; }
    else            { g_pwh[i] = h;  g_pwl[i] = l; }
}

// ---------------- kernel 2: affinity softmax + wf2 window partials ----------
// Dot phase: warp owns 2 p-rows; pix register-cached; packed f32x2 channels.
__global__ void aff_kernel(const float* __restrict__ x) {
    __shared__ float pix[16][256];
    __shared__ float wfu[9][256];
    __shared__ float lg[16][9];
    __shared__ float affs[16][9];
    int b = blockIdx.y, t = blockIdx.x, tid = threadIdx.x;
    int Y = t >> 5, X = t & 31;
    const float* xb = x + (size_t)b * 16384 * 256;
    {
        int c4 = (tid & 63) * 4;
#pragma unroll
        for (int pp = 0; pp < 4; pp++) {
            int p = pp * 4 + (tid >> 6);
            int n = (Y * 4 + (p >> 2)) * 128 + X * 4 + (p & 3);
            *(float4*)&pix[p][c4] = *(const float4*)&xb[(size_t)n * 256 + c4];
        }
#pragma unroll
        for (int ii = 0; ii < 3; ii++) {
            int i = ii * 4 + (tid >> 6);
            if (i < 9) {
                int ny = Y + (i / 3) - 1, nx = X + (i % 3) - 1;
                float4 v = make_float4(0.f, 0.f, 0.f, 0.f);
                if ((unsigned)ny < 32u && (unsigned)nx < 32u)
                    v = *(const float4*)&g_wf[((size_t)b * NW + ny * 32 + nx) * Cv + c4];
                *(float4*)&wfu[i][c4] = v;
            }
        }
    }
    __syncthreads();
    int warp = tid >> 5, lane = tid & 31;
    {
        int p0 = warp * 2, p1 = p0 + 1;
        unsigned pixb = smem_u32(&pix[0][0]) + (unsigned)lane * 8 + (unsigned)p0 * 1024;
        unsigned wfub = smem_u32(&wfu[0][0]) + (unsigned)lane * 8;
        u64 pr0[4], pr1[4];
#pragma unroll
        for (int k = 0; k < 4; k++) {
            pr0[k] = lds64(pixb + k * 256);
            pr1[k] = lds64(pixb + 1024 + k * 256);
        }
#pragma unroll
        for (int i = 0; i < 9; i++) {
            u64 s0 = 0ull, s1 = 0ull;
#pragma unroll
            for (int k = 0; k < 4; k++) {
                u64 wf = lds64(wfub + i * 1024 + k * 256);
                fma2(s0, pr0[k], wf);
                fma2(s1, pr1[k], wf);
            }
            float a0, c0, a1, c1;
            f2_unpack(a0, c0, s0);
            f2_unpack(a1, c1, s1);
            float v0 = a0 + c0, v1 = a1 + c1;
#pragma unroll
            for (int off = 16; off; off >>= 1) {
                v0 += __shfl_down_sync(0xffffffffu, v0, off);
                v1 += __shfl_down_sync(0xffffffffu, v1, off);
            }
            if (lane == 0) {
                lg[p0][i] = v0 * 0.0625f;
                lg[p1][i] = v1 * 0.0625f;
            }
        }
    }
    __syncthreads();
    if (tid < 16) {
        float m = -1e30f;
#pragma unroll
        for (int i = 0; i < 9; i++) m = fmaxf(m, lg[tid][i]);
        float e[9], sum = 0.f;
#pragma unroll
        for (int i = 0; i < 9; i++) { e[i] = __expf(lg[tid][i] - m); sum += e[i]; }
        float inv = 1.f / sum;
#pragma unroll
        for (int i = 0; i < 9; i++) affs[tid][i] = e[i] * inv;
    }
    __syncthreads();
    if (tid < 144)
        g_aff[((size_t)b * NW + t) * 144 + tid] = affs[tid / 9][tid % 9];
    if (tid >= 160 && tid < 169) {
        int i = tid - 160;
        float s = 0.f;
#pragma unroll
        for (int p = 0; p < 16; p++) s += affs[p][i];
        g_affsumraw[((size_t)b * NW + t) * 9 + i] = s;
    }
    float acc[9];
#pragma unroll
    for (int i = 0; i < 9; i++) acc[i] = 0.f;
#pragma unroll
    for (int p = 0; p < 16; p++) {
        float v = pix[p][tid];
#pragma unroll
        for (int i = 0; i < 9; i++) acc[i] = fmaf(v, affs[p][i], acc[i]);
    }
    size_t base = ((size_t)b * NW + t) * 9 * Cv;
#pragma unroll
    for (int i = 0; i < 9; i++) g_wf2raw[base + (size_t)i * Cv + tid] = acc[i];
}

// ---------------- kernel 3: fold-gather + normalize -> bf16 hi/lo -----------
__global__ void fold_kernel() {
    int b = blockIdx.y;
    int t = blockIdx.x * 4 + (threadIdx.x >> 6);
    int c = (threadIdx.x & 63) * 4;
    int Y = t >> 5, X = t & 31;
    float4 acc = make_float4(0.f, 0.f, 0.f, 0.f);
    float asum = 0.f;
#pragma unroll
    for (int i = 0; i < 9; i++) {
        int ny = Y - ((i / 3) - 1), nx = X - ((i % 3) - 1);
        if ((unsigned)ny < 32u && (unsigned)nx < 32u) {
            size_t nb = (size_t)b * NW + ny * 32 + nx;
            float4 v = *(const float4*)&g_wf2raw[(nb * 9 + i) * Cv + c];
            acc.x += v.x; acc.y += v.y; acc.z += v.z; acc.w += v.w;
            asum += g_affsumraw[nb * 9 + i];
        }
    }
    float inv = 1.f / (asum + 1e-12f);
    float f[4] = {acc.x * inv, acc.y * inv, acc.z * inv, acc.w * inv};
    size_t off = ((size_t)b * NW + t) * Cv + c;
    __nv_bfloat162 h01, h23, l01, l23;
    h01.x = __float2bfloat16(f[0]); h01.y = __float2bfloat16(f[1]);
    h23.x = __float2bfloat16(f[2]); h23.y = __float2bfloat16(f[3]);
    l01.x = __float2bfloat16(f[0] - __bfloat162float(h01.x));
    l01.y = __float2bfloat16(f[1] - __bfloat162float(h01.y));
    l23.x = __float2bfloat16(f[2] - __bfloat162float(h23.x));
    l23.y = __float2bfloat16(f[3] - __bfloat162float(h23.y));
    *(__nv_bfloat162*)&g_wf2h[off] = h01;
    *(__nv_bfloat162*)&g_wf2h[off + 2] = h23;
    *(__nv_bfloat162*)&g_wf2l[off] = l01;
    *(__nv_bfloat162*)&g_wf2l[off + 2] = l23;
}

// ---------------- GEMM via mma.sync bf16 (3-term hi/lo split) ---------------
// out[b][n][o] = sum_k A[b][n][k] * B[o][k]; A = tokens hi/lo, B = weights hi/lo.
// Block tile M=128 (tokens) x N=128 (outputs), K chunks of 32, cp.async 2-stage.
// smem stage layout: Ah @0, Al @10240, Bh @20480, Bl @30720; stage stride 40960.
// Row stride 80B (40 bf16, 64B data + 16B pad) -> conflict-free frag LDS.
#define STG_STRIDE 40960
__global__ void __launch_bounds__(256) gemm_mma(int which,
                                                const float* __restrict__ bias,
                                                int outStride) {
    extern __shared__ __align__(16) char sm[];
    int b = blockIdx.z;
    int n0 = blockIdx.x * 128, o0 = blockIdx.y * 128;
    int tid = threadIdx.x;
    int w = tid >> 5, lane = tid & 31, g = lane >> 2, t = lane & 3;
    int wm = (w >> 2) * 64, wn = (w & 3) * 32;

    const __nv_bfloat16* Ah = (which == 0 ? g_wf2h : g_aoh) + (size_t)b * NW * Cv;
    const __nv_bfloat16* Al = (which == 0 ? g_wf2l : g_aol) + (size_t)b * NW * Cv;
    const __nv_bfloat16* Bh = (which == 0 ? g_qkvwh : g_pwh);
    const __nv_bfloat16* Bl = (which == 0 ? g_qkvwl : g_pwl);
    float* out = (which == 0 ? g_qkvT : g_proj);

    unsigned smb = smem_u32(sm);
    int lr0 = tid >> 2, lq = tid & 3;
    int lr1 = lr0 + 64;
    unsigned sd0 = lr0 * 80 + lq * 16;
    unsigned sd1 = lr1 * 80 + lq * 16;

    float acc[4][4][4];
#pragma unroll
    for (int mt = 0; mt < 4; mt++)
#pragma unroll
        for (int nt = 0; nt < 4; nt++)
#pragma unroll
            for (int j = 0; j < 4; j++) acc[mt][nt][j] = 0.f;

#define ISSUE_CHUNK(kc, s) do {                                                \
    unsigned sb = smb + (s) * STG_STRIDE;                                      \
    size_t ga0 = (size_t)(n0 + lr0) * 256 + (kc) * 32 + lq * 8;                \
    size_t ga1 = (size_t)(n0 + lr1) * 256 + (kc) * 32 + lq * 8;                \
    size_t gb0 = (size_t)(o0 + lr0) * 256 + (kc) * 32 + lq * 8;                \
    size_t gb1 = (size_t)(o0 + lr1) * 256 + (kc) * 32 + lq * 8;                \
    CPA16(sb + sd0,         Ah + ga0);  CPA16(sb + sd1,         Ah + ga1);     \
    CPA16(sb + 10240 + sd0, Al + ga0);  CPA16(sb + 10240 + sd1, Al + ga1);     \
    CPA16(sb + 20480 + sd0, Bh + gb0);  CPA16(sb + 20480 + sd1, Bh + gb1);     \
    CPA16(sb + 30720 + sd0, Bl + gb0);  CPA16(sb + 30720 + sd1, Bl + gb1);     \
    CPA_COMMIT();                                                              \
} while (0)

    ISSUE_CHUNK(0, 0);
    ISSUE_CHUNK(1, 1);
#pragma unroll 1
    for (int c = 0; c < 8; c++) {
        if (c < 7) { CPA_WAIT(1); } else { CPA_WAIT(0); }
        __syncthreads();
        unsigned stage = smb + (c & 1) * STG_STRIDE;
#pragma unroll
        for (int ks = 0; ks < 2; ks++) {
            unsigned kb = ks * 32;
            unsigned bhf[4][2], blf[4][2];
#pragma unroll
            for (int nt = 0; nt < 4; nt++) {
                unsigned ba = stage + 20480 + (unsigned)(wn + nt * 8 + g) * 80 + t * 4 + kb;
                bhf[nt][0] = lds32(ba);          bhf[nt][1] = lds32(ba + 16);
                blf[nt][0] = lds32(ba + 10240);  blf[nt][1] = lds32(ba + 10256);
            }
#pragma unroll
            for (int mt = 0; mt < 4; mt++) {
                unsigned aa = stage + (unsigned)(wm + mt * 16 + g) * 80 + t * 4 + kb;
                unsigned ahf[4], alf[4];
                ahf[0] = lds32(aa);        ahf[1] = lds32(aa + 640);
                ahf[2] = lds32(aa + 16);   ahf[3] = lds32(aa + 656);
                alf[0] = lds32(aa + 10240);        alf[1] = lds32(aa + 10880);
                alf[2] = lds32(aa + 10256);        alf[3] = lds32(aa + 10896);
#pragma unroll
                for (int nt = 0; nt < 4; nt++) {
                    mma16816(acc[mt][nt], ahf, bhf[nt]);
                    mma16816(acc[mt][nt], ahf, blf[nt]);
                    mma16816(acc[mt][nt], alf, bhf[nt]);
                }
            }
        }
        __syncthreads();
        if (c < 6) ISSUE_CHUNK(c + 2, c & 1);
    }
#undef ISSUE_CHUNK

#pragma unroll
    for (int nt = 0; nt < 4; nt++) {
        int col = o0 + wn + nt * 8 + t * 2;
        float b0 = 0.f, b1 = 0.f;
        if (bias) { b0 = __ldg(&bias[col]); b1 = __ldg(&bias[col + 1]); }
#pragma unroll
        for (int mt = 0; mt < 4; mt++) {
            int row = n0 + wm + mt * 16 + g;
            float* p = out + ((size_t)b * NW + row) * outStride + col;
            *(float2*)p = make_float2(acc[mt][nt][0] + b0, acc[mt][nt][1] + b1);
            *(float2*)(p + (size_t)8 * outStride) =
                make_float2(acc[mt][nt][2] + b0, acc[mt][nt][3] + b1);
        }
    }
}

// ---------------- kernel 5: attention (token-major qkv), f32x2 --------------
__global__ void __launch_bounds__(256, 2) attn_kernel() {
    __shared__ __align__(16) float ks[128][36];
    __shared__ __align__(16) float vs[128][36];
    int b = blockIdx.z, h = blockIdx.y;
    int tid = threadIdx.x;
    int m = blockIdx.x * 256 + tid;
    const float hs = 0.17677669529663687f;
    const float* qrow = g_qkvT + ((size_t)b * NW + m) * 768 + h * 96;
    u64 q2[16], a2[16];
#pragma unroll
    for (int i = 0; i < 8; i++) {
        float4 qv = ((const float4*)qrow)[i];
        q2[2 * i] = f2_pack(qv.x * hs, qv.y * hs);
        q2[2 * i + 1] = f2_pack(qv.z * hs, qv.w * hs);
    }
#pragma unroll
    for (int i = 0; i < 16; i++) a2[i] = 0ull;
    float l = 0.f;
    unsigned ks_base = smem_u32(&ks[0][0]);
    unsigned vs_base = smem_u32(&vs[0][0]);
    for (int n0 = 0; n0 < 1024; n0 += 128) {
        __syncthreads();
#pragma unroll
        for (int r = 0; r < 4; r++) {
            int idx = r * 256 + tid;
            int n = idx >> 3, j = idx & 7;
            const float4* row = (const float4*)(g_qkvT + ((size_t)b * NW + n0 + n) * 768 + h * 96);
            *(float4*)&ks[n][j * 4] = row[8 + j];   // K at +32 floats
            *(float4*)&vs[n][j * 4] = row[16 + j];  // V at +64 floats
        }
        __syncthreads();
#pragma unroll 2
        for (int n = 0; n < 128; n += 2) {
            unsigned ka = ks_base + n * 144;
            u64 sA0 = 0ull, sA1 = 0ull, sB0 = 0ull, sB1 = 0ull;
            u64 klo, khi;
            lds128_u64(klo, khi, ka);       fma2(sA0, q2[0], klo);  fma2(sA1, q2[1], khi);
            lds128_u64(klo, khi, ka + 16);  fma2(sA0, q2[2], klo);  fma2(sA1, q2[3], khi);
            lds128_u64(klo, khi, ka + 32);  fma2(sA0, q2[4], klo);  fma2(sA1, q2[5], khi);
            lds128_u64(klo, khi, ka + 48);  fma2(sA0, q2[6], klo);  fma2(sA1, q2[7], khi);
            lds128_u64(klo, khi, ka + 64);  fma2(sA0, q2[8], klo);  fma2(sA1, q2[9], khi);
            lds128_u64(klo, khi, ka + 80);  fma2(sA0, q2[10], klo); fma2(sA1, q2[11], khi);
            lds128_u64(klo, khi, ka + 96);  fma2(sA0, q2[12], klo); fma2(sA1, q2[13], khi);
            lds128_u64(klo, khi, ka + 112); fma2(sA0, q2[14], klo); fma2(sA1, q2[15], khi);
            lds128_u64(klo, khi, ka + 144);       fma2(sB0, q2[0], klo);  fma2(sB1, q2[1], khi);
            lds128_u64(klo, khi, ka + 144 + 16);  fma2(sB0, q2[2], klo);  fma2(sB1, q2[3], khi);
            lds128_u64(klo, khi, ka + 144 + 32);  fma2(sB0, q2[4], klo);  fma2(sB1, q2[5], khi);
            lds128_u64(klo, khi, ka + 144 + 48);  fma2(sB0, q2[6], klo);  fma2(sB1, q2[7], khi);
            lds128_u64(klo, khi, ka + 144 + 64);  fma2(sB0, q2[8], klo);  fma2(sB1, q2[9], khi);
            lds128_u64(klo, khi, ka + 144 + 80);  fma2(sB0, q2[10], klo); fma2(sB1, q2[11], khi);
            lds128_u64(klo, khi, ka + 144 + 96);  fma2(sB0, q2[12], klo); fma2(sB1, q2[13], khi);
            lds128_u64(klo, khi, ka + 144 + 112); fma2(sB0, q2[14], klo); fma2(sB1, q2[15], khi);
            u64 stA = add2(sA0, sA1);
            u64 stB = add2(sB0, sB1);
            float ax, ay, bx, by;
            f2_unpack(ax, ay, stA);
            f2_unpack(bx, by, stB);
            float pA = __expf(ax + ay);
            float pB = __expf(bx + by);
            l += pA + pB;
            u64 pA2 = f2_dup(pA), pB2 = f2_dup(pB);
            unsigned va = vs_base + n * 144;
            u64 v0, v1;
#pragma unroll
            for (int i = 0; i < 8; i++) {
                lds128_u64(v0, v1, va + 16 * i);
                fma2(a2[2 * i], pA2, v0);
                fma2(a2[2 * i + 1], pA2, v1);
            }
#pragma unroll
            for (int i = 0; i < 8; i++) {
                lds128_u64(v0, v1, va + 144 + 16 * i);
                fma2(a2[2 * i], pB2, v0);
                fma2(a2[2 * i + 1], pB2, v1);
            }
        }
    }
    float inv = 1.f / l;
    size_t obase = ((size_t)b * NW + m) * Cv + h * 32;
#pragma unroll
    for (int i = 0; i < 16; i++) {
        float x, y;
        f2_unpack(x, y, a2[i]);
        x *= inv; y *= inv;
        __nv_bfloat162 hv, lv;
        hv.x = __float2bfloat16(x); hv.y = __float2bfloat16(y);
        lv.x = __float2bfloat16(x - __bfloat162float(hv.x));
        lv.y = __float2bfloat16(y - __bfloat162float(hv.y));
        *(__nv_bfloat162*)&g_aoh[obase + 2 * i] = hv;
        *(__nv_bfloat162*)&g_aol[obase + 2 * i] = lv;
    }
}

// ---------------- kernel 7: scatter back to pixels, planar output -----------
__global__ void scatter_kernel(float* __restrict__ out) {
    __shared__ float aff_s[32 * 144];
    __shared__ float r_s[3 * 34 * 33];
    int Y = blockIdx.x, b = blockIdx.y;
    int tid = threadIdx.x;
    int X = tid >> 2, px = tid & 3;
    const float* ab = g_aff + ((size_t)b * NW + Y * 32) * 144;
    for (int idx = tid; idx < 4608; idx += 128) aff_s[idx] = ab[idx];
    for (int idx = tid; idx < 3 * 34 * 33; idx += 128) r_s[idx] = 0.f;
    __syncthreads();
    float a[4][9];
#pragma unroll
    for (int py = 0; py < 4; py++)
#pragma unroll
        for (int i = 0; i < 9; i++)
            a[py][i] = aff_s[X * 144 + (py * 4 + px) * 9 + i];

    for (int c0 = 0; c0 < 256; c0 += 32) {
        __syncthreads();
        for (int idx = tid; idx < 3 * 32 * 32; idx += 128) {
            int dy = idx >> 10;
            int rem = idx & 1023;
            int Xl = rem >> 5, cc = rem & 31;
            int ny = Y + dy - 1;
            if ((unsigned)ny < 32u)
                r_s[((dy * 34) + Xl + 1) * 33 + cc] =
                    g_proj[((size_t)b * NW + ny * 32 + Xl) * Cv + c0 + cc];
        }
        __syncthreads();
#pragma unroll
        for (int py = 0; py < 4; py++) {
            size_t obase = ((size_t)b * 256 + c0) * 16384 +
                           (size_t)(Y * 4 + py) * 128 + tid;
#pragma unroll 4
            for (int c = 0; c < 32; c++) {
                float v = 0.f;
#pragma unroll
                for (int i = 0; i < 9; i++) {
                    int dy = i / 3, dx = i % 3;
                    v = fmaf(r_s[((dy * 34) + X + dx) * 33 + c], a[py][i], v);
                }
                out[obase + (size_t)c * 16384] = v;
            }
        }
    }
}

// ---------------- launch ----------------
extern "C" void kernel_launch(void* const* d_in, const int* in_sizes, int n_in,
                              void* d_out, int out_size) {
    const float* x = nullptr; const float* qkv_w = nullptr;
    const float* proj_w = nullptr; const float* proj_b = nullptr;
    for (int i = 0; i < n_in; i++) {
        int s = in_sizes[i];
        if (s == 8 * 16384 * 256) x = (const float*)d_in[i];
        else if (s == 768 * 256)  qkv_w = (const float*)d_in[i];
        else if (s == 256 * 256)  proj_w = (const float*)d_in[i];
        else if (s == 256)        proj_b = (const float*)d_in[i];
    }
    float* out = (float*)d_out;

    const int DSMEM = 2 * STG_STRIDE;   // 80 KB: 2 stages x (Ah,Al,Bh,Bl)
    cudaFuncSetAttribute(gemm_mma, cudaFuncAttributeMaxDynamicSharedMemorySize, DSMEM);

    pool_kernel<<<dim3(256, 8), 256>>>(x);
    conv_w<<<768, 256>>>(qkv_w, 0, 768 * 256);
    conv_w<<<256, 256>>>(proj_w, 1, 256 * 256);
    aff_kernel<<<dim3(1024, 8), 256>>>(x);
    fold_kernel<<<dim3(256, 8), 256>>>();
    gemm_mma<<<dim3(8, 6, 8), 256, DSMEM>>>(0, nullptr, 768);
    attn_kernel<<<dim3(4, 8, 8), 256>>>();
    gemm_mma<<<dim3(8, 2, 8), 256, DSMEM>>>(1, proj_b, 256);
    scatter_kernel<<<dim3(32, 8), 128>>>(out);
}

// round 9
// speedup vs baseline: 1.9951x; 1.4744x over previous
#include <cuda_runtime.h>
#include <cuda_bf16.h>
#include <math.h>
#include <stdint.h>

#define Bv 8
#define Cv 256
#define NW 1024      // 32*32 super tokens
#define NHEADS 8
#define HD 32

// ---------------- scratch (static device memory; no allocs) ----------------
__device__ float g_wf[Bv * NW * Cv];                 // (b, t, c)
__device__ float g_aff[Bv * NW * 16 * 9];            // (b, t, p, i)
__device__ float g_wf2raw[(size_t)Bv * NW * 9 * Cv]; // (b, t, i, c)
__device__ float g_affsumraw[Bv * NW * 9];           // (b, t, i)
__device__ __nv_bfloat16 g_wf2h[Bv * NW * Cv];       // tokens hi (b, t, c)
__device__ __nv_bfloat16 g_wf2l[Bv * NW * Cv];       // tokens lo
__device__ __nv_bfloat16 g_qkvwh[768 * 256];         // qkv weight hi (o,k)
__device__ __nv_bfloat16 g_qkvwl[768 * 256];
__device__ __nv_bfloat16 g_pwh[256 * 256];           // proj weight hi (o,k)
__device__ __nv_bfloat16 g_pwl[256 * 256];
__device__ __nv_bfloat16 g_qkh[(size_t)Bv * NW * 768];  // qkv out hi (b, n, o)
__device__ __nv_bfloat16 g_qkl[(size_t)Bv * NW * 768];  // qkv out lo
__device__ unsigned short g_vTh[(size_t)Bv * 8 * 32 * 1024]; // V^T hi (b,h,d,n)
__device__ unsigned short g_vTl[(size_t)Bv * 8 * 32 * 1024]; // V^T lo
__device__ __nv_bfloat16 g_aoh[Bv * NW * Cv];        // attn out hi (b, n, c)
__device__ __nv_bfloat16 g_aol[Bv * NW * Cv];        // attn out lo
__device__ float g_proj[(size_t)Bv * NW * Cv];       // (b, n, o)

// ---------------- f32x2 packed-math helpers (sm_103a) ----------------
typedef unsigned long long u64;
__device__ __forceinline__ u64 f2_dup(float a) {
    u64 d; asm("mov.b64 %0, {%1, %1};" : "=l"(d) : "f"(a)); return d;
}
__device__ __forceinline__ void f2_unpack(float& a, float& b, u64 d) {
    asm("mov.b64 {%0, %1}, %2;" : "=f"(a), "=f"(b) : "l"(d));
}
__device__ __forceinline__ void fma2(u64& c, u64 a, u64 b) {
    asm("fma.rn.f32x2 %0, %1, %2, %0;" : "+l"(c) : "l"(a), "l"(b));
}
__device__ __forceinline__ u64 lds64(unsigned saddr) {
    u64 v;
    asm volatile("ld.shared.b64 %0, [%1];" : "=l"(v) : "r"(saddr));
    return v;
}
__device__ __forceinline__ unsigned lds32(unsigned saddr) {
    unsigned v;
    asm volatile("ld.shared.b32 %0, [%1];" : "=r"(v) : "r"(saddr));
    return v;
}
__device__ __forceinline__ unsigned smem_u32(const void* p) {
    unsigned a;
    asm("{ .reg .u64 t; cvta.to.shared.u64 t, %1; cvt.u32.u64 %0, t; }" : "=r"(a) : "l"(p));
    return a;
}
// pack: low half = lo, high half = hi (PTX: first src -> upper)
__device__ __forceinline__ unsigned pack_bf16x2(float lo, float hi) {
    unsigned d;
    asm("cvt.rn.bf16x2.f32 %0, %1, %2;" : "=r"(d) : "f"(hi), "f"(lo));
    return d;
}

// ---------------- mma.sync + cp.async helpers (portable sm_80+) -------------
__device__ __forceinline__ void mma16816(float* c, const unsigned* a, const unsigned* b) {
    asm volatile(
        "mma.sync.aligned.m16n8k16.row.col.f32.bf16.bf16.f32 "
        "{%0,%1,%2,%3}, {%4,%5,%6,%7}, {%8,%9}, {%0,%1,%2,%3};"
        : "+f"(c[0]), "+f"(c[1]), "+f"(c[2]), "+f"(c[3])
        : "r"(a[0]), "r"(a[1]), "r"(a[2]), "r"(a[3]), "r"(b[0]), "r"(b[1]));
}
#define CPA16(dst, src) \
    asm volatile("cp.async.ca.shared.global [%0], [%1], 16;" :: "r"(dst), "l"(src))
#define CPA_COMMIT() asm volatile("cp.async.commit_group;" ::: "memory")
#define CPA_WAIT(n)  asm volatile("cp.async.wait_group %0;" :: "n"(n) : "memory")

// ---------------- kernel 1: 4x4 average pool -> wf (float4) ----------------
__global__ void pool_kernel(const float* __restrict__ x) {
    int b = blockIdx.y;
    int t = blockIdx.x * 4 + (threadIdx.x >> 6);
    int c4 = (threadIdx.x & 63) * 4;
    int Y = t >> 5, X = t & 31;
    const float* xb = x + (size_t)b * 16384 * 256;
    float4 s = make_float4(0.f, 0.f, 0.f, 0.f);
#pragma unroll
    for (int py = 0; py < 4; py++)
#pragma unroll
        for (int px = 0; px < 4; px++) {
            int n = (Y * 4 + py) * 128 + X * 4 + px;
            float4 v = *(const float4*)&xb[(size_t)n * 256 + c4];
            s.x += v.x; s.y += v.y; s.z += v.z; s.w += v.w;
        }
    s.x *= (1.f / 16.f); s.y *= (1.f / 16.f); s.z *= (1.f / 16.f); s.w *= (1.f / 16.f);
    *(float4*)&g_wf[((size_t)b * NW + t) * Cv + c4] = s;
}

// ---------------- weight conversion: fp32 -> bf16 hi/lo ----------------
__global__ void conv_w(const float* __restrict__ src, int which, int nElt) {
    int i = blockIdx.x * 256 + threadIdx.x;
    if (i >= nElt) return;
    float x = src[i];
    __nv_bfloat16 h = __float2bfloat16(x);
    __nv_bfloat16 l = __float2bfloat16(x - __bfloat162float(h));
    if (which == 0) { g_qkvwh[i] = h; g_qkvwl[i] = l; }
    else            { g_pwh[i] = h;  g_pwl[i] = l; }
}

// ---------------- kernel 2: affinity softmax + wf2 window partials ----------
__global__ void aff_kernel(const float* __restrict__ x) {
    __shared__ float pix[16][256];
    __shared__ float wfu[9][256];
    __shared__ float lg[16][9];
    __shared__ float affs[16][9];
    int b = blockIdx.y, t = blockIdx.x, tid = threadIdx.x;
    int Y = t >> 5, X = t & 31;
    const float* xb = x + (size_t)b * 16384 * 256;
    {
        int c4 = (tid & 63) * 4;
#pragma unroll
        for (int pp = 0; pp < 4; pp++) {
            int p = pp * 4 + (tid >> 6);
            int n = (Y * 4 + (p >> 2)) * 128 + X * 4 + (p & 3);
            *(float4*)&pix[p][c4] = *(const float4*)&xb[(size_t)n * 256 + c4];
        }
#pragma unroll
        for (int ii = 0; ii < 3; ii++) {
            int i = ii * 4 + (tid >> 6);
            if (i < 9) {
                int ny = Y + (i / 3) - 1, nx = X + (i % 3) - 1;
                float4 v = make_float4(0.f, 0.f, 0.f, 0.f);
                if ((unsigned)ny < 32u && (unsigned)nx < 32u)
                    v = *(const float4*)&g_wf[((size_t)b * NW + ny * 32 + nx) * Cv + c4];
                *(float4*)&wfu[i][c4] = v;
            }
        }
    }
    __syncthreads();
    int warp = tid >> 5, lane = tid & 31;
    {
        int p0 = warp * 2, p1 = p0 + 1;
        unsigned pixb = smem_u32(&pix[0][0]) + (unsigned)lane * 8 + (unsigned)p0 * 1024;
        unsigned wfub = smem_u32(&wfu[0][0]) + (unsigned)lane * 8;
        u64 pr0[4], pr1[4];
#pragma unroll
        for (int k = 0; k < 4; k++) {
            pr0[k] = lds64(pixb + k * 256);
            pr1[k] = lds64(pixb + 1024 + k * 256);
        }
#pragma unroll
        for (int i = 0; i < 9; i++) {
            u64 s0 = 0ull, s1 = 0ull;
#pragma unroll
            for (int k = 0; k < 4; k++) {
                u64 wf = lds64(wfub + i * 1024 + k * 256);
                fma2(s0, pr0[k], wf);
                fma2(s1, pr1[k], wf);
            }
            float a0, c0, a1, c1;
            f2_unpack(a0, c0, s0);
            f2_unpack(a1, c1, s1);
            float v0 = a0 + c0, v1 = a1 + c1;
#pragma unroll
            for (int off = 16; off; off >>= 1) {
                v0 += __shfl_down_sync(0xffffffffu, v0, off);
                v1 += __shfl_down_sync(0xffffffffu, v1, off);
            }
            if (lane == 0) {
                lg[p0][i] = v0 * 0.0625f;
                lg[p1][i] = v1 * 0.0625f;
            }
        }
    }
    __syncthreads();
    if (tid < 16) {
        float m = -1e30f;
#pragma unroll
        for (int i = 0; i < 9; i++) m = fmaxf(m, lg[tid][i]);
        float e[9], sum = 0.f;
#pragma unroll
        for (int i = 0; i < 9; i++) { e[i] = __expf(lg[tid][i] - m); sum += e[i]; }
        float inv = 1.f / sum;
#pragma unroll
        for (int i = 0; i < 9; i++) affs[tid][i] = e[i] * inv;
    }
    __syncthreads();
    if (tid < 144)
        g_aff[((size_t)b * NW + t) * 144 + tid] = affs[tid / 9][tid % 9];
    if (tid >= 160 && tid < 169) {
        int i = tid - 160;
        float s = 0.f;
#pragma unroll
        for (int p = 0; p < 16; p++) s += affs[p][i];
        g_affsumraw[((size_t)b * NW + t) * 9 + i] = s;
    }
    float acc[9];
#pragma unroll
    for (int i = 0; i < 9; i++) acc[i] = 0.f;
#pragma unroll
    for (int p = 0; p < 16; p++) {
        float v = pix[p][tid];
#pragma unroll
        for (int i = 0; i < 9; i++) acc[i] = fmaf(v, affs[p][i], acc[i]);
    }
    size_t base = ((size_t)b * NW + t) * 9 * Cv;
#pragma unroll
    for (int i = 0; i < 9; i++) g_wf2raw[base + (size_t)i * Cv + tid] = acc[i];
}

// ---------------- kernel 3: fold-gather + normalize -> bf16 hi/lo -----------
__global__ void fold_kernel() {
    int b = blockIdx.y;
    int t = blockIdx.x * 4 + (threadIdx.x >> 6);
    int c = (threadIdx.x & 63) * 4;
    int Y = t >> 5, X = t & 31;
    float4 acc = make_float4(0.f, 0.f, 0.f, 0.f);
    float asum = 0.f;
#pragma unroll
    for (int i = 0; i < 9; i++) {
        int ny = Y - ((i / 3) - 1), nx = X - ((i % 3) - 1);
        if ((unsigned)ny < 32u && (unsigned)nx < 32u) {
            size_t nb = (size_t)b * NW + ny * 32 + nx;
            float4 v = *(const float4*)&g_wf2raw[(nb * 9 + i) * Cv + c];
            acc.x += v.x; acc.y += v.y; acc.z += v.z; acc.w += v.w;
            asum += g_affsumraw[nb * 9 + i];
        }
    }
    float inv = 1.f / (asum + 1e-12f);
    float f[4] = {acc.x * inv, acc.y * inv, acc.z * inv, acc.w * inv};
    size_t off = ((size_t)b * NW + t) * Cv + c;
    __nv_bfloat162 h01, h23, l01, l23;
    h01.x = __float2bfloat16(f[0]); h01.y = __float2bfloat16(f[1]);
    h23.x = __float2bfloat16(f[2]); h23.y = __float2bfloat16(f[3]);
    l01.x = __float2bfloat16(f[0] - __bfloat162float(h01.x));
    l01.y = __float2bfloat16(f[1] - __bfloat162float(h01.y));
    l23.x = __float2bfloat16(f[2] - __bfloat162float(h23.x));
    l23.y = __float2bfloat16(f[3] - __bfloat162float(h23.y));
    *(__nv_bfloat162*)&g_wf2h[off] = h01;
    *(__nv_bfloat162*)&g_wf2h[off + 2] = h23;
    *(__nv_bfloat162*)&g_wf2l[off] = l01;
    *(__nv_bfloat162*)&g_wf2l[off + 2] = l23;
}

// ---------------- GEMM via mma.sync bf16 (3-term hi/lo split) ---------------
// which==0 (qkv): out bf16 hi/lo token-major + V^T copies. which==1 (proj): f32+bias.
#define STG_STRIDE 40960
__global__ void __launch_bounds__(256) gemm_mma(int which,
                                                const float* __restrict__ bias,
                                                int outStride) {
    extern __shared__ __align__(16) char sm[];
    int b = blockIdx.z;
    int n0 = blockIdx.x * 128, o0 = blockIdx.y * 128;
    int tid = threadIdx.x;
    int w = tid >> 5, lane = tid & 31, g = lane >> 2, t = lane & 3;
    int wm = (w >> 2) * 64, wn = (w & 3) * 32;

    const __nv_bfloat16* Ah = (which == 0 ? g_wf2h : g_aoh) + (size_t)b * NW * Cv;
    const __nv_bfloat16* Al = (which == 0 ? g_wf2l : g_aol) + (size_t)b * NW * Cv;
    const __nv_bfloat16* Bh = (which == 0 ? g_qkvwh : g_pwh);
    const __nv_bfloat16* Bl = (which == 0 ? g_qkvwl : g_pwl);

    unsigned smb = smem_u32(sm);
    int lr0 = tid >> 2, lq = tid & 3;
    int lr1 = lr0 + 64;
    unsigned sd0 = lr0 * 80 + lq * 16;
    unsigned sd1 = lr1 * 80 + lq * 16;

    float acc[4][4][4];
#pragma unroll
    for (int mt = 0; mt < 4; mt++)
#pragma unroll
        for (int nt = 0; nt < 4; nt++)
#pragma unroll
            for (int j = 0; j < 4; j++) acc[mt][nt][j] = 0.f;

#define ISSUE_CHUNK(kc, s) do {                                                \
    unsigned sb = smb + (s) * STG_STRIDE;                                      \
    size_t ga0 = (size_t)(n0 + lr0) * 256 + (kc) * 32 + lq * 8;                \
    size_t ga1 = (size_t)(n0 + lr1) * 256 + (kc) * 32 + lq * 8;                \
    size_t gb0 = (size_t)(o0 + lr0) * 256 + (kc) * 32 + lq * 8;                \
    size_t gb1 = (size_t)(o0 + lr1) * 256 + (kc) * 32 + lq * 8;                \
    CPA16(sb + sd0,         Ah + ga0);  CPA16(sb + sd1,         Ah + ga1);     \
    CPA16(sb + 10240 + sd0, Al + ga0);  CPA16(sb + 10240 + sd1, Al + ga1);     \
    CPA16(sb + 20480 + sd0, Bh + gb0);  CPA16(sb + 20480 + sd1, Bh + gb1);     \
    CPA16(sb + 30720 + sd0, Bl + gb0);  CPA16(sb + 30720 + sd1, Bl + gb1);     \
    CPA_COMMIT();                                                              \
} while (0)

    ISSUE_CHUNK(0, 0);
    ISSUE_CHUNK(1, 1);
#pragma unroll 1
    for (int c = 0; c < 8; c++) {
        if (c < 7) { CPA_WAIT(1); } else { CPA_WAIT(0); }
        __syncthreads();
        unsigned stage = smb + (c & 1) * STG_STRIDE;
#pragma unroll
        for (int ks = 0; ks < 2; ks++) {
            unsigned kb = ks * 32;
            unsigned bhf[4][2], blf[4][2];
#pragma unroll
            for (int nt = 0; nt < 4; nt++) {
                unsigned ba = stage + 20480 + (unsigned)(wn + nt * 8 + g) * 80 + t * 4 + kb;
                bhf[nt][0] = lds32(ba);          bhf[nt][1] = lds32(ba + 16);
                blf[nt][0] = lds32(ba + 10240);  blf[nt][1] = lds32(ba + 10256);
            }
#pragma unroll
            for (int mt = 0; mt < 4; mt++) {
                unsigned aa = stage + (unsigned)(wm + mt * 16 + g) * 80 + t * 4 + kb;
                unsigned ahf[4], alf[4];
                ahf[0] = lds32(aa);        ahf[1] = lds32(aa + 640);
                ahf[2] = lds32(aa + 16);   ahf[3] = lds32(aa + 656);
                alf[0] = lds32(aa + 10240);        alf[1] = lds32(aa + 10880);
                alf[2] = lds32(aa + 10256);        alf[3] = lds32(aa + 10896);
#pragma unroll
                for (int nt = 0; nt < 4; nt++) {
                    mma16816(acc[mt][nt], ahf, bhf[nt]);
                    mma16816(acc[mt][nt], ahf, blf[nt]);
                    mma16816(acc[mt][nt], alf, bhf[nt]);
                }
            }
        }
        __syncthreads();
        if (c < 6) ISSUE_CHUNK(c + 2, c & 1);
    }
#undef ISSUE_CHUNK

    if (which == 1) {
#pragma unroll
        for (int nt = 0; nt < 4; nt++) {
            int col = o0 + wn + nt * 8 + t * 2;
            float b0 = __ldg(&bias[col]), b1 = __ldg(&bias[col + 1]);
#pragma unroll
            for (int mt = 0; mt < 4; mt++) {
                int row = n0 + wm + mt * 16 + g;
                float* p = g_proj + ((size_t)b * NW + row) * 256 + col;
                *(float2*)p = make_float2(acc[mt][nt][0] + b0, acc[mt][nt][1] + b1);
                *(float2*)(p + (size_t)8 * 256) =
                    make_float2(acc[mt][nt][2] + b0, acc[mt][nt][3] + b1);
            }
        }
    } else {
#pragma unroll
        for (int nt = 0; nt < 4; nt++) {
            int col = o0 + wn + nt * 8 + t * 2;
            int cm = col % 96, hh = col / 96;
#pragma unroll
            for (int mt = 0; mt < 4; mt++) {
                int row = n0 + wm + mt * 16 + g;
#pragma unroll
                for (int rr = 0; rr < 2; rr++) {
                    int r = row + rr * 8;
                    float v0 = acc[mt][nt][rr * 2], v1 = acc[mt][nt][rr * 2 + 1];
                    unsigned hpair = pack_bf16x2(v0, v1);
                    float h0f = __uint_as_float(hpair << 16);
                    float h1f = __uint_as_float(hpair & 0xffff0000u);
                    unsigned lpair = pack_bf16x2(v0 - h0f, v1 - h1f);
                    size_t oo = ((size_t)b * NW + r) * 768 + col;
                    *(unsigned*)&g_qkh[oo] = hpair;
                    *(unsigned*)&g_qkl[oo] = lpair;
                    if (cm >= 64) {
                        int d = cm - 64;
                        size_t vb = (((size_t)b * 8 + hh) * 32 + d) * 1024 + r;
                        g_vTh[vb] = (unsigned short)(hpair & 0xffffu);
                        g_vTh[vb + 1024] = (unsigned short)(hpair >> 16);
                        g_vTl[vb] = (unsigned short)(lpair & 0xffffu);
                        g_vTl[vb + 1024] = (unsigned short)(lpair >> 16);
                    }
                }
            }
        }
    }
}

// ---------------- kernel 5: flash-MMA attention ----------------
// Block: 128 queries of one (b,h); 8 warps x m16. Key tiles of 128.
// smem: Qh@0, Ql@10240, Kh@20480, Kl@30720 (128 rows x 80B),
//       Vth@40960, Vtl@51840 (40 rows x 272B; row32 = ones for l).
#define ATT_SMEM (40960 + 2 * 10880)
__global__ void __launch_bounds__(256) attn_mma() {
    extern __shared__ __align__(16) char asm_[];
    int qb = blockIdx.x, h = blockIdx.y, b = blockIdx.z;
    int m0 = qb * 128;
    int tid = threadIdx.x, w = tid >> 5, lane = tid & 31, g = lane >> 2, t = lane & 3;
    unsigned sb = smem_u32(asm_);
    const unsigned Qh = sb, Ql = sb + 10240, Kh = sb + 20480, Kl = sb + 30720;
    const unsigned Vh = sb + 40960, Vl = sb + 51840;
    const float hs = 0.17677669529663687f;

    // load Q tile (128 x 32 bf16 hi/lo), rows pitch 80
    {
        const __nv_bfloat16* qh = g_qkh + ((size_t)b * NW + m0) * 768 + h * 96;
        const __nv_bfloat16* ql = g_qkl + ((size_t)b * NW + m0) * 768 + h * 96;
#pragma unroll
        for (int it = 0; it < 2; it++) {
            int idx = tid + it * 256;
            int row = idx >> 2, q = idx & 3;
            uint4 vh = *(const uint4*)(qh + (size_t)row * 768 + q * 8);
            uint4 vl = *(const uint4*)(ql + (size_t)row * 768 + q * 8);
            *(uint4*)(asm_ + row * 80 + q * 16) = vh;
            *(uint4*)(asm_ + 10240 + row * 80 + q * 16) = vl;
        }
    }
    // init vt rows 32..39 (ones row 32, zeros elsewhere); persists across tiles
    for (int idx = tid; idx < 544; idx += 256) {
        int row = 32 + idx / 68, wd = idx % 68;
        ((unsigned*)(asm_ + 40960))[row * 68 + wd] =
            (row == 32 && wd < 64) ? 0x3F803F80u : 0u;
        ((unsigned*)(asm_ + 51840))[row * 68 + wd] = 0u;
    }
    __syncthreads();
    // Q fragments (persist in regs); warp m-range = w*16
    unsigned ah[2][4], al[2][4];
    {
        unsigned qa = Qh + (unsigned)(w * 16 + g) * 80 + t * 4;
        unsigned qa_l = Ql + (unsigned)(w * 16 + g) * 80 + t * 4;
#pragma unroll
        for (int kt2 = 0; kt2 < 2; kt2++) {
            unsigned o = kt2 * 32;
            ah[kt2][0] = lds32(qa + o);       ah[kt2][1] = lds32(qa + o + 640);
            ah[kt2][2] = lds32(qa + o + 16);  ah[kt2][3] = lds32(qa + o + 656);
            al[kt2][0] = lds32(qa_l + o);      al[kt2][1] = lds32(qa_l + o + 640);
            al[kt2][2] = lds32(qa_l + o + 16); al[kt2][3] = lds32(qa_l + o + 656);
        }
    }

    float O[5][4];
#pragma unroll
    for (int v = 0; v < 5; v++)
#pragma unroll
        for (int j = 0; j < 4; j++) O[v][j] = 0.f;

#pragma unroll 1
    for (int kt = 0; kt < 8; kt++) {
        int n0 = kt * 128;
        __syncthreads();
        {
            const __nv_bfloat16* kh = g_qkh + ((size_t)b * NW + n0) * 768 + h * 96 + 32;
            const __nv_bfloat16* kl = g_qkl + ((size_t)b * NW + n0) * 768 + h * 96 + 32;
#pragma unroll
            for (int it = 0; it < 2; it++) {
                int idx = tid + it * 256;
                int row = idx >> 2, q = idx & 3;
                uint4 vh = *(const uint4*)(kh + (size_t)row * 768 + q * 8);
                uint4 vl = *(const uint4*)(kl + (size_t)row * 768 + q * 8);
                *(uint4*)(asm_ + 20480 + row * 80 + q * 16) = vh;
                *(uint4*)(asm_ + 30720 + row * 80 + q * 16) = vl;
            }
            int d = tid >> 3, seg = tid & 7;
            const unsigned short* vth = g_vTh + (((size_t)b * 8 + h) * 32 + d) * 1024 + n0 + seg * 16;
            const unsigned short* vtl = g_vTl + (((size_t)b * 8 + h) * 32 + d) * 1024 + n0 + seg * 16;
            *(uint4*)(asm_ + 40960 + d * 272 + seg * 32) = *(const uint4*)vth;
            *(uint4*)(asm_ + 40960 + d * 272 + seg * 32 + 16) = *(const uint4*)(vth + 8);
            *(uint4*)(asm_ + 51840 + d * 272 + seg * 32) = *(const uint4*)vtl;
            *(uint4*)(asm_ + 51840 + d * 272 + seg * 32 + 16) = *(const uint4*)(vtl + 8);
        }
        __syncthreads();

        unsigned pa_h[8][4], pa_l[8][4];
#pragma unroll
        for (int j = 0; j < 16; j++) {
            float s[4] = {0.f, 0.f, 0.f, 0.f};
            unsigned kbase = Kh + (unsigned)(j * 8 + g) * 80 + t * 4;
            unsigned kbase_l = Kl + (unsigned)(j * 8 + g) * 80 + t * 4;
#pragma unroll
            for (int kt2 = 0; kt2 < 2; kt2++) {
                unsigned o = kt2 * 32;
                unsigned bh[2] = {lds32(kbase + o), lds32(kbase + o + 16)};
                unsigned bl[2] = {lds32(kbase_l + o), lds32(kbase_l + o + 16)};
                mma16816(s, ah[kt2], bh);
                mma16816(s, ah[kt2], bl);
                mma16816(s, al[kt2], bh);
            }
            float p0 = __expf(s[0] * hs), p1 = __expf(s[1] * hs);
            float p2 = __expf(s[2] * hs), p3 = __expf(s[3] * hs);
            unsigned h01 = pack_bf16x2(p0, p1);
            unsigned h23 = pack_bf16x2(p2, p3);
            unsigned l01 = pack_bf16x2(p0 - __uint_as_float(h01 << 16),
                                       p1 - __uint_as_float(h01 & 0xffff0000u));
            unsigned l23 = pack_bf16x2(p2 - __uint_as_float(h23 << 16),
                                       p3 - __uint_as_float(h23 & 0xffff0000u));
            int kk = j >> 1, hf = (j & 1) * 2;
            pa_h[kk][hf] = h01; pa_h[kk][hf + 1] = h23;
            pa_l[kk][hf] = l01; pa_l[kk][hf + 1] = l23;
        }
#pragma unroll
        for (int v = 0; v < 5; v++) {
            unsigned vb = Vh + (unsigned)(v * 8 + g) * 272 + t * 4;
            unsigned vb_l = Vl + (unsigned)(v * 8 + g) * 272 + t * 4;
#pragma unroll
            for (int kk = 0; kk < 8; kk++) {
                unsigned o = kk * 32;
                unsigned bh[2] = {lds32(vb + o), lds32(vb + o + 16)};
                unsigned bl[2] = {lds32(vb_l + o), lds32(vb_l + o + 16)};
                mma16816(O[v], pa_h[kk], bh);
                mma16816(O[v], pa_h[kk], bl);
                mma16816(O[v], pa_l[kk], bh);
            }
        }
    }
    // epilogue: l from ones column (col 32 = n-tile 4, c0/c2 of t==0 lanes)
    float lg = __shfl_sync(0xffffffffu, O[4][0], lane & 28);
    float lg8 = __shfl_sync(0xffffffffu, O[4][2], lane & 28);
    float inv = 1.f / lg, inv8 = 1.f / lg8;
    size_t ob = ((size_t)b * NW + m0 + w * 16 + g) * 256 + h * 32;
    size_t ob8 = ob + (size_t)8 * 256;
#pragma unroll
    for (int v = 0; v < 4; v++) {
        int d = v * 8 + t * 2;
        float x0 = O[v][0] * inv, x1 = O[v][1] * inv;
        float x2 = O[v][2] * inv8, x3 = O[v][3] * inv8;
        unsigned hp0 = pack_bf16x2(x0, x1);
        unsigned lp0 = pack_bf16x2(x0 - __uint_as_float(hp0 << 16),
                                   x1 - __uint_as_float(hp0 & 0xffff0000u));
        unsigned hp1 = pack_bf16x2(x2, x3);
        unsigned lp1 = pack_bf16x2(x2 - __uint_as_float(hp1 << 16),
                                   x3 - __uint_as_float(hp1 & 0xffff0000u));
        *(unsigned*)&g_aoh[ob + d] = hp0;
        *(unsigned*)&g_aol[ob + d] = lp0;
        *(unsigned*)&g_aoh[ob8 + d] = hp1;
        *(unsigned*)&g_aol[ob8 + d] = lp1;
    }
}

// ---------------- kernel 7: scatter back to pixels, planar output -----------
__global__ void scatter_kernel(float* __restrict__ out) {
    __shared__ float aff_s[32 * 144];
    __shared__ float r_s[3 * 34 * 33];
    int Y = blockIdx.x, b = blockIdx.y;
    int tid = threadIdx.x;
    int X = tid >> 2, px = tid & 3;
    const float* ab = g_aff + ((size_t)b * NW + Y * 32) * 144;
    for (int idx = tid; idx < 4608; idx += 128) aff_s[idx] = ab[idx];
    for (int idx = tid; idx < 3 * 34 * 33; idx += 128) r_s[idx] = 0.f;
    __syncthreads();
    float a[4][9];
#pragma unroll
    for (int py = 0; py < 4; py++)
#pragma unroll
        for (int i = 0; i < 9; i++)
            a[py][i] = aff_s[X * 144 + (py * 4 + px) * 9 + i];

    for (int c0 = 0; c0 < 256; c0 += 32) {
        __syncthreads();
        for (int idx = tid; idx < 3 * 32 * 32; idx += 128) {
            int dy = idx >> 10;
            int rem = idx & 1023;
            int Xl = rem >> 5, cc = rem & 31;
            int ny = Y + dy - 1;
            if ((unsigned)ny < 32u)
                r_s[((dy * 34) + Xl + 1) * 33 + cc] =
                    g_proj[((size_t)b * NW + ny * 32 + Xl) * Cv + c0 + cc];
        }
        __syncthreads();
#pragma unroll
        for (int py = 0; py < 4; py++) {
            size_t obase = ((size_t)b * 256 + c0) * 16384 +
                           (size_t)(Y * 4 + py) * 128 + tid;
#pragma unroll 4
            for (int c = 0; c < 32; c++) {
                float v = 0.f;
#pragma unroll
                for (int i = 0; i < 9; i++) {
                    int dy = i / 3, dx = i % 3;
                    v = fmaf(r_s[((dy * 34) + X + dx) * 33 + c], a[py][i], v);
                }
                out[obase + (size_t)c * 16384] = v;
            }
        }
    }
}

// ---------------- launch ----------------
extern "C" void kernel_launch(void* const* d_in, const int* in_sizes, int n_in,
                              void* d_out, int out_size) {
    const float* x = nullptr; const float* qkv_w = nullptr;
    const float* proj_w = nullptr; const float* proj_b = nullptr;
    for (int i = 0; i < n_in; i++) {
        int s = in_sizes[i];
        if (s == 8 * 16384 * 256) x = (const float*)d_in[i];
        else if (s == 768 * 256)  qkv_w = (const float*)d_in[i];
        else if (s == 256 * 256)  proj_w = (const float*)d_in[i];
        else if (s == 256)        proj_b = (const float*)d_in[i];
    }
    float* out = (float*)d_out;

    const int DSMEM = 2 * STG_STRIDE;
    cudaFuncSetAttribute(gemm_mma, cudaFuncAttributeMaxDynamicSharedMemorySize, DSMEM);
    cudaFuncSetAttribute(attn_mma, cudaFuncAttributeMaxDynamicSharedMemorySize, ATT_SMEM);

    pool_kernel<<<dim3(256, 8), 256>>>(x);
    conv_w<<<768, 256>>>(qkv_w, 0, 768 * 256);
    conv_w<<<256, 256>>>(proj_w, 1, 256 * 256);
    aff_kernel<<<dim3(1024, 8), 256>>>(x);
    fold_kernel<<<dim3(256, 8), 256>>>();
    gemm_mma<<<dim3(8, 6, 8), 256, DSMEM>>>(0, nullptr, 768);
    attn_mma<<<dim3(8, 8, 8), 256, ATT_SMEM>>>();
    gemm_mma<<<dim3(8, 2, 8), 256, DSMEM>>>(1, proj_b, 256);
    scatter_kernel<<<dim3(32, 8), 128>>>(out);
}